// round 3
// baseline (speedup 1.0000x reference)
#include <cuda_runtime.h>
#include <cuda_bf16.h>
#include <math.h>
#include <stdint.h>

// ---------------- problem constants ----------------
#define BB 8192
#define DV 1024
#define DT 768
#define LD_X 1797      // DV + DT + 4 + 1
#define HH 256
#define CC 5
#define GHH 128
#define KNN 8
#define FDIM 512       // 2*H
#define GI 773         // FD + C + H
#define NIMG 512
#define NEGV (-1000000000.0f)

typedef unsigned long long u64;

// ---------------- scratch (device globals, allocation-free) ----------------
__device__ float g_xn[(size_t)BB * 1792];      // normalized [xv | xt]
__device__ float g_base[(size_t)BB * FDIM];    // base_fused
__device__ float g_cp[(size_t)BB * CC];        // class_prior
__device__ float g_agg[(size_t)BB * FDIM];     // knn aggregate (reused twice)
__device__ float g_t1[(size_t)BB * HH];        // ctx hidden
__device__ float g_tok[(size_t)BB * HH];       // spatial_token
__device__ float g_gin[(size_t)BB * GI];       // gate input concat
__device__ float g_hid[(size_t)BB * GHH];      // gate hidden
__device__ float g_gp[(size_t)BB * 2];         // gate probs
__device__ float g_ent[BB];                    // per-row entropy
__device__ float g_fused[(size_t)BB * FDIM];   // gated fused (updated in place)
__device__ float g_u1[(size_t)BB * FDIM];      // gu hidden
__device__ float g_h[(size_t)BB * HH];         // classifier hidden
__device__ float g_w[(size_t)BB * KNN];        // knn softmax weights
__device__ int   g_nidx[(size_t)BB * KNN];     // knn indices
__device__ int   g_cnt[NIMG];
__device__ int   g_off[NIMG + 1];
__device__ int   g_cur[NIMG];
__device__ int   g_bucket[BB];

// ---------------- packed f32x2 helpers ----------------
__device__ __forceinline__ u64 pack2(float lo, float hi) {
    u64 r; asm("mov.b64 %0, {%1, %2};" : "=l"(r) : "f"(lo), "f"(hi)); return r;
}
__device__ __forceinline__ void unpack2(float& lo, float& hi, u64 v) {
    asm("mov.b64 {%0, %1}, %2;" : "=f"(lo), "=f"(hi) : "l"(v));
}
__device__ __forceinline__ u64 ffma2(u64 a, u64 b, u64 c) {
    u64 d; asm("fma.rn.f32x2 %0, %1, %2, %3;" : "=l"(d) : "l"(a), "l"(b), "l"(c)); return d;
}

// ---------------- LayerNorm (per-row, fused for v and t segments) ----------------
__global__ void ln_kernel(const float* __restrict__ x,
                          const float* __restrict__ gv, const float* __restrict__ bv,
                          const float* __restrict__ gt, const float* __restrict__ bt)
{
    int row = blockIdx.x;
    const float* xr = x + (size_t)row * LD_X;
    float* outr = g_xn + (size_t)row * 1792;
    __shared__ float red[256];
    int tid = threadIdx.x;

    // ---- v segment (1024) ----
    float s = 0.f;
    for (int c = tid; c < DV; c += 256) s += xr[c];
    red[tid] = s; __syncthreads();
    for (int o = 128; o > 0; o >>= 1) { if (tid < o) red[tid] += red[tid + o]; __syncthreads(); }
    float m = red[0] / (float)DV;
    __syncthreads();
    float s2 = 0.f;
    for (int c = tid; c < DV; c += 256) { float d = xr[c] - m; s2 += d * d; }
    red[tid] = s2; __syncthreads();
    for (int o = 128; o > 0; o >>= 1) { if (tid < o) red[tid] += red[tid + o]; __syncthreads(); }
    float r = rsqrtf(red[0] / (float)DV + 1e-5f);
    __syncthreads();
    for (int c = tid; c < DV; c += 256) outr[c] = (xr[c] - m) * r * gv[c] + bv[c];

    // ---- t segment (768) ----
    s = 0.f;
    for (int c = tid; c < DT; c += 256) s += xr[DV + c];
    red[tid] = s; __syncthreads();
    for (int o = 128; o > 0; o >>= 1) { if (tid < o) red[tid] += red[tid + o]; __syncthreads(); }
    m = red[0] / (float)DT;
    __syncthreads();
    s2 = 0.f;
    for (int c = tid; c < DT; c += 256) { float d = xr[DV + c] - m; s2 += d * d; }
    red[tid] = s2; __syncthreads();
    for (int o = 128; o > 0; o >>= 1) { if (tid < o) red[tid] += red[tid + o]; __syncthreads(); }
    r = rsqrtf(red[0] / (float)DT + 1e-5f);
    __syncthreads();
    for (int c = tid; c < DT; c += 256) outr[DV + c] = (xr[DV + c] - m) * r * gt[c] + bt[c];
}

// ---------------- tiled fp32 GEMM (FFMA2 mainloop): C = epi(A @ W + bias) ----------------
// 128x128 CTA tile, TBK=16, 256 threads, 8x8 microtile computed as 8x(4 f32x2).
// A tile stored DUPLICATED in smem ((a,a) pairs) so the FFMA2 broadcast operand
// is a single conflict-free LDS.64; B pairs are natural 64-bit lanes.
#define TBM 128
#define TBN 128
#define TBK 16
#define E_BIAS  0
#define E_RELU  1
#define E_RESID 2
#define E_BN    3

template<int EPI>
__global__ void __launch_bounds__(256)
gemm_f32(const float* __restrict__ A, int lda,
         const float* __restrict__ W,         // K x N, row-major
         const float* __restrict__ bias,
         float* __restrict__ C, int ldc,
         int N, int K,
         const float* __restrict__ scale, const float* __restrict__ shift,
         const float* __restrict__ resid, int ldr, float alpha)
{
    __shared__ float sA2[TBK][2 * TBM];   // duplicated pairs: [k][2m]=[k][2m+1]=A
    __shared__ float sB[TBK][TBN];
    int tid = threadIdx.x;
    int bm = blockIdx.y * TBM;
    int bn = blockIdx.x * TBN;
    int tx = tid & 15;   // 16 col groups
    int ty = tid >> 4;   // 16 row groups

    u64 acc2[8][4];
    #pragma unroll
    for (int i = 0; i < 8; i++)
        #pragma unroll
        for (int j = 0; j < 4; j++) acc2[i][j] = 0ull;

    for (int k0 = 0; k0 < K; k0 += TBK) {
        // A: 128x16 elems, 8 per thread; e = tid*8+i -> m=e>>4, k=e&15
        #pragma unroll
        for (int i = 0; i < 8; i++) {
            int e = tid * 8 + i;
            int m = e >> 4, k = e & 15;
            int kk = k0 + k;
            float v = (kk < K) ? A[(size_t)(bm + m) * lda + kk] : 0.f;
            *(u64*)&sA2[k][2 * m] = pack2(v, v);
        }
        // B: 16x128 elems, 8 per thread; e = tid*8+i -> r=e>>7, c=e&127
        #pragma unroll
        for (int i = 0; i < 8; i++) {
            int e = tid * 8 + i;
            int r = e >> 7, c = e & 127;
            int kk = k0 + r;
            sB[r][c] = (kk < K) ? W[(size_t)kk * N + bn + c] : 0.f;
        }
        __syncthreads();
        #pragma unroll
        for (int k = 0; k < TBK; k++) {
            u64 a2[8], b2[4];
            #pragma unroll
            for (int i = 0; i < 8; i++)
                a2[i] = *(const u64*)&sA2[k][(ty * 8 + i) * 2];
            // b pairs: cols (tx*4 + {0,1}), (tx*4 + {2,3}), (64+tx*4 + {0,1}), (64+tx*4 + {2,3})
            {
                ulonglong2 v0 = *(const ulonglong2*)&sB[k][tx * 4];
                ulonglong2 v1 = *(const ulonglong2*)&sB[k][64 + tx * 4];
                b2[0] = v0.x; b2[1] = v0.y; b2[2] = v1.x; b2[3] = v1.y;
            }
            #pragma unroll
            for (int i = 0; i < 8; i++)
                #pragma unroll
                for (int j = 0; j < 4; j++)
                    acc2[i][j] = ffma2(a2[i], b2[j], acc2[i][j]);
        }
        __syncthreads();
    }

    #pragma unroll
    for (int i = 0; i < 8; i++) {
        int m = bm + ty * 8 + i;
        #pragma unroll
        for (int j = 0; j < 4; j++) {
            float vlo, vhi;
            unpack2(vlo, vhi, acc2[i][j]);
            int nbase = bn + ((j < 2) ? (tx * 4 + j * 2) : (64 + tx * 4 + (j - 2) * 2));
            #pragma unroll
            for (int h = 0; h < 2; h++) {
                int n = nbase + h;
                float v = (h ? vhi : vlo) + bias[n];
                if (EPI == E_RELU) v = fmaxf(v, 0.f);
                else if (EPI == E_RESID) v = resid[(size_t)m * ldr + n] + alpha * v;
                else if (EPI == E_BN) {
                    v = v * (scale[n] * rsqrtf(1.f + 1e-5f)) + shift[n];
                    v = fmaxf(v, 0.f);
                }
                C[(size_t)m * ldc + n] = v;
            }
        }
    }
}

// ---------------- class_prior: softmax(base @ W_cp + b_cp), warp per row ----------------
__global__ void cp_kernel(const float* __restrict__ Wcp, const float* __restrict__ bcp)
{
    int warp = threadIdx.x >> 5, lane = threadIdx.x & 31;
    int row = blockIdx.x * 8 + warp;
    if (row >= BB) return;
    const float* f = g_base + (size_t)row * FDIM;
    float acc[CC] = {0, 0, 0, 0, 0};
    for (int k = lane; k < FDIM; k += 32) {
        float fv = f[k];
        #pragma unroll
        for (int c = 0; c < CC; c++) acc[c] += fv * Wcp[k * CC + c];
    }
    #pragma unroll
    for (int c = 0; c < CC; c++)
        for (int o = 16; o; o >>= 1) acc[c] += __shfl_xor_sync(0xffffffff, acc[c], o);
    if (lane == 0) {
        float z[CC], mx = -1e30f, sum = 0.f;
        #pragma unroll
        for (int c = 0; c < CC; c++) { z[c] = acc[c] + bcp[c]; mx = fmaxf(mx, z[c]); }
        #pragma unroll
        for (int c = 0; c < CC; c++) { z[c] = expf(z[c] - mx); sum += z[c]; }
        #pragma unroll
        for (int c = 0; c < CC; c++) g_cp[(size_t)row * CC + c] = z[c] / sum;
    }
}

// ---------------- KNN: bucket by image, per-point top-8 ----------------
__global__ void zero_cnt_kernel() {
    int t = blockIdx.x * blockDim.x + threadIdx.x;
    if (t < NIMG) { g_cnt[t] = 0; g_cur[t] = 0; }
}
__global__ void count_kernel(const float* __restrict__ x) {
    int i = blockIdx.x * blockDim.x + threadIdx.x;
    if (i >= BB) return;
    int im = (int)x[(size_t)i * LD_X + 1796];
    atomicAdd(&g_cnt[im], 1);
}
__global__ void prefix_kernel() {
    if (blockIdx.x == 0 && threadIdx.x == 0) {
        int s = 0;
        for (int i = 0; i < NIMG; i++) { g_off[i] = s; s += g_cnt[i]; }
        g_off[NIMG] = s;
    }
}
__global__ void fill_kernel(const float* __restrict__ x) {
    int i = blockIdx.x * blockDim.x + threadIdx.x;
    if (i >= BB) return;
    int im = (int)x[(size_t)i * LD_X + 1796];
    int p = atomicAdd(&g_cur[im], 1);
    g_bucket[g_off[im] + p] = i;
}

__device__ __forceinline__ void topk_insert(float* val, int* ind, float s, int j) {
    if (s > val[KNN - 1]) {
        int p = KNN - 1;
        while (p > 0 && s > val[p - 1]) { val[p] = val[p - 1]; ind[p] = ind[p - 1]; p--; }
        val[p] = s; ind[p] = j;
    }
}

__global__ void knn_topk_kernel(const float* __restrict__ x)
{
    int i = blockIdx.x * blockDim.x + threadIdx.x;
    if (i >= BB) return;
    const float* xi = x + (size_t)i * LD_X;
    float cx = xi[1792], cy = xi[1793];
    int im = (int)xi[1796];
    float sqi = cx * cx + cy * cy;

    float val[KNN]; int ind[KNN];
    #pragma unroll
    for (int k = 0; k < KNN; k++) { val[k] = NEGV; ind[k] = 0; }

    int s = g_off[im], e = g_off[im + 1];
    int m = 0;
    for (int p = s; p < e; p++) {
        int j = g_bucket[p];
        if (j == i) continue;
        const float* xj = x + (size_t)j * LD_X;
        float jx = xj[1792], jy = xj[1793];
        float sqj = jx * jx + jy * jy;
        float d2 = sqi + sqj - 2.f * (cx * jx + cy * jy);
        float sim = -sqrtf(fmaxf(d2, 0.f));
        m++;
        topk_insert(val, ind, sim, j);
    }
    if (m == 0) {  // no same-image neighbor: global fallback (self excluded)
        for (int j = 0; j < BB; j++) {
            if (j == i) continue;
            const float* xj = x + (size_t)j * LD_X;
            float jx = xj[1792], jy = xj[1793];
            float sqj = jx * jx + jy * jy;
            float d2 = sqi + sqj - 2.f * (cx * jx + cy * jy);
            float sim = -sqrtf(fmaxf(d2, 0.f));
            topk_insert(val, ind, sim, j);
        }
    }
    float mx = val[0];
    float w[KNN], sum = 0.f;
    #pragma unroll
    for (int k = 0; k < KNN; k++) { w[k] = expf(val[k] - mx); sum += w[k]; }
    float inv = 1.f / sum;
    #pragma unroll
    for (int k = 0; k < KNN; k++) {
        g_w[(size_t)i * KNN + k] = w[k] * inv;
        g_nidx[(size_t)i * KNN + k] = ind[k];
    }
}

// ---------------- weighted gather: out[i,:] = sum_k w[i,k] * F[idx[i,k],:] ----------------
__global__ void gather_kernel(const float* __restrict__ F, float* __restrict__ out)
{
    int row = blockIdx.x;
    __shared__ float sw[KNN];
    __shared__ int   si[KNN];
    if (threadIdx.x < KNN) {
        sw[threadIdx.x] = g_w[(size_t)row * KNN + threadIdx.x];
        si[threadIdx.x] = g_nidx[(size_t)row * KNN + threadIdx.x];
    }
    __syncthreads();
    for (int c = threadIdx.x; c < FDIM; c += blockDim.x) {
        float acc = 0.f;
        #pragma unroll
        for (int k = 0; k < KNN; k++) acc += sw[k] * F[(size_t)si[k] * FDIM + c];
        out[(size_t)row * FDIM + c] = acc;
    }
}

// ---------------- gate_in concat ----------------
__global__ void gin_kernel()
{
    int t = blockIdx.x * blockDim.x + threadIdx.x;
    if (t >= BB * GI) return;
    int row = t / GI, c = t % GI;
    float v;
    if (c < FDIM)          v = g_base[(size_t)row * FDIM + c];
    else if (c < FDIM + CC) v = g_cp[(size_t)row * CC + (c - FDIM)];
    else                    v = g_tok[(size_t)row * HH + (c - FDIM - CC)];
    g_gin[t] = v;
}

// ---------------- gate second layer + softmax + entropy ----------------
__global__ void gate2_kernel(const float* __restrict__ Wg2, const float* __restrict__ bg2)
{
    int warp = threadIdx.x >> 5, lane = threadIdx.x & 31;
    int row = blockIdx.x * 8 + warp;
    if (row >= BB) return;
    float a0 = 0.f, a1 = 0.f;
    const float* h = g_hid + (size_t)row * GHH;
    for (int k = lane; k < GHH; k += 32) {
        float hv = h[k];
        a0 += hv * Wg2[k * 2];
        a1 += hv * Wg2[k * 2 + 1];
    }
    for (int o = 16; o; o >>= 1) {
        a0 += __shfl_xor_sync(0xffffffff, a0, o);
        a1 += __shfl_xor_sync(0xffffffff, a1, o);
    }
    if (lane == 0) {
        float z0 = a0 + bg2[0], z1 = a1 + bg2[1];
        float mx = fmaxf(z0, z1);
        float e0 = expf(z0 - mx), e1 = expf(z1 - mx);
        float sinv = 1.f / (e0 + e1);
        float p0 = e0 * sinv, p1 = e1 * sinv;
        g_gp[(size_t)row * 2] = p0;
        g_gp[(size_t)row * 2 + 1] = p1;
        g_ent[row] = -(p0 * logf(p0 + 1e-8f) + p1 * logf(p1 + 1e-8f));
    }
}

// ---------------- fused = [fv*g0, ft*g1] ----------------
__global__ void fmul_kernel()
{
    int t = blockIdx.x * blockDim.x + threadIdx.x;
    if (t >= BB * FDIM) return;
    int row = t >> 9, c = t & 511;
    g_fused[t] = g_base[t] * g_gp[(size_t)row * 2 + (c >= HH ? 1 : 0)];
}

// ---------------- final classifier layer 2 -> logits ----------------
__global__ void c2_kernel(const float* __restrict__ Wc2, const float* __restrict__ bc2,
                          float* __restrict__ out)
{
    int warp = threadIdx.x >> 5, lane = threadIdx.x & 31;
    int row = blockIdx.x * 8 + warp;
    if (row >= BB) return;
    const float* h = g_h + (size_t)row * HH;
    float acc[CC] = {0, 0, 0, 0, 0};
    for (int k = lane; k < HH; k += 32) {
        float hv = h[k];
        #pragma unroll
        for (int c = 0; c < CC; c++) acc[c] += hv * Wc2[k * CC + c];
    }
    #pragma unroll
    for (int c = 0; c < CC; c++)
        for (int o = 16; o; o >>= 1) acc[c] += __shfl_xor_sync(0xffffffff, acc[c], o);
    if (lane == 0) {
        #pragma unroll
        for (int c = 0; c < CC; c++) out[(size_t)row * CC + c] = acc[c] + bc2[c];
    }
}

// ---------------- entropy mean (deterministic tree reduce) ----------------
__global__ void ent_reduce_kernel(float* __restrict__ out)
{
    __shared__ float red[256];
    int tid = threadIdx.x;
    float s = 0.f;
    for (int t = tid; t < BB; t += 256) s += g_ent[t];
    red[tid] = s; __syncthreads();
    for (int o = 128; o > 0; o >>= 1) { if (tid < o) red[tid] += red[tid + o]; __syncthreads(); }
    if (tid == 0) out[0] = red[0] / (float)BB * 0.01f;
}

// ---------------- launch ----------------
static float* sym_f(const void* p) { return (float*)p; }

extern "C" void kernel_launch(void* const* d_in, const int* in_sizes, int n_in,
                              void* d_out, int out_size)
{
    const float* x     = (const float*)d_in[0];
    const float* ln_vg = (const float*)d_in[1];
    const float* ln_vb = (const float*)d_in[2];
    const float* ln_tg = (const float*)d_in[3];
    const float* ln_tb = (const float*)d_in[4];
    const float* W_v   = (const float*)d_in[5];
    const float* b_v   = (const float*)d_in[6];
    const float* W_t   = (const float*)d_in[7];
    const float* b_t   = (const float*)d_in[8];
    const float* W_cp  = (const float*)d_in[9];
    const float* b_cp  = (const float*)d_in[10];
    const float* W_ctx1 = (const float*)d_in[11];
    const float* b_ctx1 = (const float*)d_in[12];
    const float* W_ctx2 = (const float*)d_in[13];
    const float* b_ctx2 = (const float*)d_in[14];
    const float* W_g1  = (const float*)d_in[15];
    const float* b_g1  = (const float*)d_in[16];
    const float* W_g2  = (const float*)d_in[17];
    const float* b_g2  = (const float*)d_in[18];
    const float* W_gu1 = (const float*)d_in[19];
    const float* b_gu1 = (const float*)d_in[20];
    const float* W_gu2 = (const float*)d_in[21];
    const float* b_gu2 = (const float*)d_in[22];
    const float* W_c1  = (const float*)d_in[23];
    const float* b_c1  = (const float*)d_in[24];
    const float* bn_g  = (const float*)d_in[25];
    const float* bn_b  = (const float*)d_in[26];
    const float* W_c2  = (const float*)d_in[27];
    const float* b_c2  = (const float*)d_in[28];
    float* out = (float*)d_out;

    void *p_xn, *p_base, *p_agg, *p_t1, *p_tok, *p_gin, *p_hid, *p_fused, *p_u1, *p_h;
    cudaGetSymbolAddress(&p_xn, g_xn);
    cudaGetSymbolAddress(&p_base, g_base);
    cudaGetSymbolAddress(&p_agg, g_agg);
    cudaGetSymbolAddress(&p_t1, g_t1);
    cudaGetSymbolAddress(&p_tok, g_tok);
    cudaGetSymbolAddress(&p_gin, g_gin);
    cudaGetSymbolAddress(&p_hid, g_hid);
    cudaGetSymbolAddress(&p_fused, g_fused);
    cudaGetSymbolAddress(&p_u1, g_u1);
    cudaGetSymbolAddress(&p_h, g_h);
    float* xn    = sym_f(p_xn);
    float* base  = sym_f(p_base);
    float* agg   = sym_f(p_agg);
    float* t1    = sym_f(p_t1);
    float* tok   = sym_f(p_tok);
    float* gin   = sym_f(p_gin);
    float* hid   = sym_f(p_hid);
    float* fused = sym_f(p_fused);
    float* u1    = sym_f(p_u1);
    float* hbuf  = sym_f(p_h);

    // 1) LayerNorm both segments
    ln_kernel<<<BB, 256>>>(x, ln_vg, ln_vb, ln_tg, ln_tb);

    // 2) fv / ft GEMMs -> base_fused columns
    dim3 gA(HH / TBN, BB / TBM);   // (2, 64)
    gemm_f32<E_BIAS><<<gA, 256>>>(xn, 1792, W_v, b_v, base, FDIM, HH, DV,
                                  nullptr, nullptr, nullptr, 0, 0.f);
    gemm_f32<E_BIAS><<<gA, 256>>>(xn + DV, 1792, W_t, b_t, base + HH, FDIM, HH, DT,
                                  nullptr, nullptr, nullptr, 0, 0.f);

    // 3) class prior
    cp_kernel<<<BB / 8, 256>>>(W_cp, b_cp);

    // 4) KNN (shared between both aggregates)
    zero_cnt_kernel<<<2, 256>>>();
    count_kernel<<<BB / 256, 256>>>(x);
    prefix_kernel<<<1, 32>>>();
    fill_kernel<<<BB / 256, 256>>>(x);
    knn_topk_kernel<<<BB / 256, 256>>>(x);

    // 5) neigh_agg over base_fused -> spatial_token
    gather_kernel<<<BB, 128>>>(base, agg);
    gemm_f32<E_RELU><<<gA, 256>>>(agg, FDIM, W_ctx1, b_ctx1, t1, HH, HH, FDIM,
                                  nullptr, nullptr, nullptr, 0, 0.f);
    gemm_f32<E_BIAS><<<gA, 256>>>(t1, HH, W_ctx2, b_ctx2, tok, HH, HH, HH,
                                  nullptr, nullptr, nullptr, 0, 0.f);

    // 6) gate
    gin_kernel<<<(BB * GI + 255) / 256, 256>>>();
    dim3 gG(GHH / TBN, BB / TBM);  // (1, 64)
    gemm_f32<E_RELU><<<gG, 256>>>(gin, GI, W_g1, b_g1, hid, GHH, GHH, GI,
                                  nullptr, nullptr, nullptr, 0, 0.f);
    gate2_kernel<<<BB / 8, 256>>>(W_g2, b_g2);

    // 7) fused = gated base, spatial update, residual
    fmul_kernel<<<(BB * FDIM + 255) / 256, 256>>>();
    gather_kernel<<<BB, 128>>>(fused, agg);
    dim3 gF(FDIM / TBN, BB / TBM); // (4, 64)
    gemm_f32<E_RELU><<<gF, 256>>>(agg, FDIM, W_gu1, b_gu1, u1, FDIM, FDIM, FDIM,
                                  nullptr, nullptr, nullptr, 0, 0.f);
    gemm_f32<E_RESID><<<gF, 256>>>(u1, FDIM, W_gu2, b_gu2, fused, FDIM, FDIM, FDIM,
                                   nullptr, nullptr, fused, FDIM, 0.5f);

    // 8) classifier
    gemm_f32<E_BN><<<gA, 256>>>(fused, FDIM, W_c1, b_c1, hbuf, HH, HH, FDIM,
                                bn_g, bn_b, nullptr, 0, 0.f);
    c2_kernel<<<BB / 8, 256>>>(W_c2, b_c2, out);

    // 9) entropy scalar -> last output element
    ent_reduce_kernel<<<1, 256>>>(out + (out_size - 1));
}

// round 6
// speedup vs baseline: 2.2553x; 2.2553x over previous
#include <cuda_runtime.h>
#include <cuda_bf16.h>
#include <math.h>
#include <stdint.h>

// ---------------- problem constants ----------------
#define BB 8192
#define DV 1024
#define DT 768
#define LD_X 1797      // DV + DT + 4 + 1
#define HH 256
#define CC 5
#define GHH 128
#define KNN 8
#define FDIM 512       // 2*H
#define GI 773         // FD + C + H
#define NIMG 512
#define NEGV (-1000000000.0f)

// ---------------- scratch (device globals, allocation-free) ----------------
__device__ float g_xn[(size_t)BB * 1792];      // normalized [xv | xt]
__device__ float g_base[(size_t)BB * FDIM];    // base_fused
__device__ float g_cp[(size_t)BB * CC];        // class_prior
__device__ float g_agg[(size_t)BB * FDIM];     // knn aggregate (reused twice)
__device__ float g_t1[(size_t)BB * HH];        // ctx hidden
__device__ float g_tok[(size_t)BB * HH];       // spatial_token
__device__ float g_gin[(size_t)BB * GI];       // gate input concat
__device__ float g_hid[(size_t)BB * GHH];      // gate hidden
__device__ float g_gp[(size_t)BB * 2];         // gate probs
__device__ float g_ent[BB];                    // per-row entropy
__device__ float g_fused[(size_t)BB * FDIM];   // gated fused (updated in place)
__device__ float g_u1[(size_t)BB * FDIM];      // gu hidden
__device__ float g_h[(size_t)BB * HH];         // classifier hidden
__device__ float g_w[(size_t)BB * KNN];        // knn softmax weights
__device__ int   g_nidx[(size_t)BB * KNN];     // knn indices
__device__ int   g_cnt[NIMG];
__device__ int   g_off[NIMG + 1];
__device__ int   g_cur[NIMG];
__device__ int   g_bucket[BB];

// ---------------- LayerNorm (per-row, fused for v and t segments) ----------------
__global__ void ln_kernel(const float* __restrict__ x,
                          const float* __restrict__ gv, const float* __restrict__ bv,
                          const float* __restrict__ gt, const float* __restrict__ bt)
{
    int row = blockIdx.x;
    const float* xr = x + (size_t)row * LD_X;
    float* outr = g_xn + (size_t)row * 1792;
    __shared__ float red[256];
    int tid = threadIdx.x;

    float s = 0.f;
    for (int c = tid; c < DV; c += 256) s += xr[c];
    red[tid] = s; __syncthreads();
    for (int o = 128; o > 0; o >>= 1) { if (tid < o) red[tid] += red[tid + o]; __syncthreads(); }
    float m = red[0] / (float)DV;
    __syncthreads();
    float s2 = 0.f;
    for (int c = tid; c < DV; c += 256) { float d = xr[c] - m; s2 += d * d; }
    red[tid] = s2; __syncthreads();
    for (int o = 128; o > 0; o >>= 1) { if (tid < o) red[tid] += red[tid + o]; __syncthreads(); }
    float r = rsqrtf(red[0] / (float)DV + 1e-5f);
    __syncthreads();
    for (int c = tid; c < DV; c += 256) outr[c] = (xr[c] - m) * r * gv[c] + bv[c];

    s = 0.f;
    for (int c = tid; c < DT; c += 256) s += xr[DV + c];
    red[tid] = s; __syncthreads();
    for (int o = 128; o > 0; o >>= 1) { if (tid < o) red[tid] += red[tid + o]; __syncthreads(); }
    m = red[0] / (float)DT;
    __syncthreads();
    s2 = 0.f;
    for (int c = tid; c < DT; c += 256) { float d = xr[DV + c] - m; s2 += d * d; }
    red[tid] = s2; __syncthreads();
    for (int o = 128; o > 0; o >>= 1) { if (tid < o) red[tid] += red[tid + o]; __syncthreads(); }
    r = rsqrtf(red[0] / (float)DT + 1e-5f);
    __syncthreads();
    for (int c = tid; c < DT; c += 256) outr[DV + c] = (xr[DV + c] - m) * r * gt[c] + bt[c];
}

// ---------------- 3xBF16 mma.sync GEMM: C[M,N] = epi(A[M,K] @ W[K,N] + bias) ----------------
// CTA 128x128, 256 threads (8 warps as 4m x 2n), warp tile 32m x 64n.
// K-chunk = 32 fp32. A stored [m][k] bf16 pairs; B transposed to [n][k].
// Row stride 20 words (16 data + 4 pad) -> conflict-free fragment LDS.
#define E_BIAS  0
#define E_RELU  1
#define E_RESID 2
#define E_BN    3
#define SRW 20   // smem row stride in 32-bit words

__device__ __forceinline__ void mma16816(float* d, const uint32_t* a, uint32_t b0, uint32_t b1) {
    asm volatile(
        "mma.sync.aligned.m16n8k16.row.col.f32.bf16.bf16.f32 "
        "{%0,%1,%2,%3}, {%4,%5,%6,%7}, {%8,%9}, {%0,%1,%2,%3};"
        : "+f"(d[0]), "+f"(d[1]), "+f"(d[2]), "+f"(d[3])
        : "r"(a[0]), "r"(a[1]), "r"(a[2]), "r"(a[3]), "r"(b0), "r"(b1));
}

__device__ __forceinline__ void split2(float x, float y, uint32_t& hi, uint32_t& lo) {
    __nv_bfloat162 h = __floats2bfloat162_rn(x, y);     // x -> low half
    float xr = x - __bfloat162float(__low2bfloat16(h));
    float yr = y - __bfloat162float(__high2bfloat16(h));
    __nv_bfloat162 l = __floats2bfloat162_rn(xr, yr);
    hi = *(uint32_t*)&h;
    lo = *(uint32_t*)&l;
}

template<int EPI>
__global__ void __launch_bounds__(256)
gemm_mma(const float* __restrict__ A, int lda,
         const float* __restrict__ W,          // K x N row-major
         const float* __restrict__ bias,
         float* __restrict__ C, int ldc,
         int N, int K,
         const float* __restrict__ scale, const float* __restrict__ shift,
         const float* __restrict__ resid, int ldr, float alpha)
{
    __shared__ uint32_t sAhi[128 * SRW], sAlo[128 * SRW];
    __shared__ uint32_t sBhi[128 * SRW], sBlo[128 * SRW];

    int tid = threadIdx.x;
    int lane = tid & 31, wid = tid >> 5;
    int bm = blockIdx.y * 128, bn = blockIdx.x * 128;
    int wm = (wid >> 1) * 32, wn = (wid & 1) * 64;

    float acc[2][8][4];
    #pragma unroll
    for (int mf = 0; mf < 2; mf++)
        #pragma unroll
        for (int nf = 0; nf < 8; nf++)
            #pragma unroll
            for (int q = 0; q < 4; q++) acc[mf][nf][q] = 0.f;

    // A staging: row = tid>>3 (+32 per pass, 4 passes), kq = (tid&7)*4
    int a_r = tid >> 3, a_kq = (tid & 7) * 4;
    // B staging: n = tid&127, kbase = (tid>>7)*16
    int b_n = tid & 127, b_kb = (tid >> 7) * 16;

    float aReg[4][4];   // [pass][4 floats]
    float bReg[16];

    int nch = (K + 31) / 32;
    const bool avec = ((lda & 3) == 0) && ((K & 31) == 0);

    // ---- preload chunk 0 ----
    {
        int k0 = 0;
        if (avec) {
            #pragma unroll
            for (int p = 0; p < 4; p++)
                *(float4*)aReg[p] = *(const float4*)&A[(size_t)(bm + a_r + p * 32) * lda + k0 + a_kq];
        } else {
            #pragma unroll
            for (int p = 0; p < 4; p++)
                #pragma unroll
                for (int q = 0; q < 4; q++) {
                    int kk = k0 + a_kq + q;
                    aReg[p][q] = (kk < K) ? A[(size_t)(bm + a_r + p * 32) * lda + kk] : 0.f;
                }
        }
        #pragma unroll
        for (int q = 0; q < 16; q++) {
            int kk = k0 + b_kb + q;
            bReg[q] = (kk < K) ? W[(size_t)kk * N + bn + b_n] : 0.f;
        }
    }

    for (int ch = 0; ch < nch; ch++) {
        __syncthreads();   // previous compute done reading smem
        // ---- STS (split into hi/lo bf16) ----
        #pragma unroll
        for (int p = 0; p < 4; p++) {
            uint32_t h0, l0, h1, l1;
            split2(aReg[p][0], aReg[p][1], h0, l0);
            split2(aReg[p][2], aReg[p][3], h1, l1);
            int idx = (a_r + p * 32) * SRW + (a_kq >> 1);
            *(uint2*)&sAhi[idx] = make_uint2(h0, h1);
            *(uint2*)&sAlo[idx] = make_uint2(l0, l1);
        }
        #pragma unroll
        for (int j = 0; j < 4; j++) {
            uint32_t h0, l0, h1, l1;
            split2(bReg[4 * j], bReg[4 * j + 1], h0, l0);
            split2(bReg[4 * j + 2], bReg[4 * j + 3], h1, l1);
            int idx = b_n * SRW + (b_kb >> 1) + 2 * j;
            *(uint2*)&sBhi[idx] = make_uint2(h0, h1);
            *(uint2*)&sBlo[idx] = make_uint2(l0, l1);
        }
        __syncthreads();

        // ---- prefetch next chunk while computing ----
        if (ch + 1 < nch) {
            int k0 = (ch + 1) * 32;
            if (avec) {
                #pragma unroll
                for (int p = 0; p < 4; p++)
                    *(float4*)aReg[p] = *(const float4*)&A[(size_t)(bm + a_r + p * 32) * lda + k0 + a_kq];
            } else {
                #pragma unroll
                for (int p = 0; p < 4; p++)
                    #pragma unroll
                    for (int q = 0; q < 4; q++) {
                        int kk = k0 + a_kq + q;
                        aReg[p][q] = (kk < K) ? A[(size_t)(bm + a_r + p * 32) * lda + kk] : 0.f;
                    }
            }
            #pragma unroll
            for (int q = 0; q < 16; q++) {
                int kk = k0 + b_kb + q;
                bReg[q] = (kk < K) ? W[(size_t)kk * N + bn + b_n] : 0.f;
            }
        }

        // ---- compute: 2 k16-steps ----
        #pragma unroll
        for (int ks = 0; ks < 2; ks++) {
            int kw = ks * 8 + (lane & 3);
            int r0 = wm + (lane >> 2);
            uint32_t ah[2][4], al[2][4];
            #pragma unroll
            for (int mf = 0; mf < 2; mf++) {
                int r = r0 + mf * 16;
                ah[mf][0] = sAhi[r * SRW + kw];
                ah[mf][1] = sAhi[(r + 8) * SRW + kw];
                ah[mf][2] = sAhi[r * SRW + kw + 4];
                ah[mf][3] = sAhi[(r + 8) * SRW + kw + 4];
                al[mf][0] = sAlo[r * SRW + kw];
                al[mf][1] = sAlo[(r + 8) * SRW + kw];
                al[mf][2] = sAlo[r * SRW + kw + 4];
                al[mf][3] = sAlo[(r + 8) * SRW + kw + 4];
            }
            #pragma unroll
            for (int nf = 0; nf < 8; nf++) {
                int n = wn + nf * 8 + (lane >> 2);
                uint32_t bh0 = sBhi[n * SRW + kw], bh1 = sBhi[n * SRW + kw + 4];
                uint32_t bl0 = sBlo[n * SRW + kw], bl1 = sBlo[n * SRW + kw + 4];
                #pragma unroll
                for (int mf = 0; mf < 2; mf++) {
                    mma16816(acc[mf][nf], ah[mf], bh0, bh1);
                    mma16816(acc[mf][nf], ah[mf], bl0, bl1);
                    mma16816(acc[mf][nf], al[mf], bh0, bh1);
                }
            }
        }
    }

    // ---- epilogue ----
    int mb = bm + wm + (lane >> 2);
    int nb = bn + wn + 2 * (lane & 3);
    #pragma unroll
    for (int mf = 0; mf < 2; mf++) {
        #pragma unroll
        for (int nf = 0; nf < 8; nf++) {
            int n0 = nb + nf * 8;
            #pragma unroll
            for (int half = 0; half < 2; half++) {   // rows r, r+8
                int m = mb + mf * 16 + half * 8;
                float v0 = acc[mf][nf][half * 2 + 0] + bias[n0];
                float v1 = acc[mf][nf][half * 2 + 1] + bias[n0 + 1];
                if (EPI == E_RELU) { v0 = fmaxf(v0, 0.f); v1 = fmaxf(v1, 0.f); }
                else if (EPI == E_RESID) {
                    v0 = resid[(size_t)m * ldr + n0] + alpha * v0;
                    v1 = resid[(size_t)m * ldr + n0 + 1] + alpha * v1;
                }
                else if (EPI == E_BN) {
                    float rs = rsqrtf(1.f + 1e-5f);
                    v0 = fmaxf(v0 * (scale[n0] * rs) + shift[n0], 0.f);
                    v1 = fmaxf(v1 * (scale[n0 + 1] * rs) + shift[n0 + 1], 0.f);
                }
                *(float2*)&C[(size_t)m * ldc + n0] = make_float2(v0, v1);
            }
        }
    }
}

// ---------------- class_prior: softmax(base @ W_cp + b_cp), warp per row ----------------
__global__ void cp_kernel(const float* __restrict__ Wcp, const float* __restrict__ bcp)
{
    int warp = threadIdx.x >> 5, lane = threadIdx.x & 31;
    int row = blockIdx.x * 8 + warp;
    if (row >= BB) return;
    const float* f = g_base + (size_t)row * FDIM;
    float acc[CC] = {0, 0, 0, 0, 0};
    for (int k = lane; k < FDIM; k += 32) {
        float fv = f[k];
        #pragma unroll
        for (int c = 0; c < CC; c++) acc[c] += fv * Wcp[k * CC + c];
    }
    #pragma unroll
    for (int c = 0; c < CC; c++)
        for (int o = 16; o; o >>= 1) acc[c] += __shfl_xor_sync(0xffffffff, acc[c], o);
    if (lane == 0) {
        float z[CC], mx = -1e30f, sum = 0.f;
        #pragma unroll
        for (int c = 0; c < CC; c++) { z[c] = acc[c] + bcp[c]; mx = fmaxf(mx, z[c]); }
        #pragma unroll
        for (int c = 0; c < CC; c++) { z[c] = expf(z[c] - mx); sum += z[c]; }
        #pragma unroll
        for (int c = 0; c < CC; c++) g_cp[(size_t)row * CC + c] = z[c] / sum;
    }
}

// ---------------- KNN: bucket by image, per-point top-8 ----------------
__global__ void zero_cnt_kernel() {
    int t = blockIdx.x * blockDim.x + threadIdx.x;
    if (t < NIMG) { g_cnt[t] = 0; g_cur[t] = 0; }
}
__global__ void count_kernel(const float* __restrict__ x) {
    int i = blockIdx.x * blockDim.x + threadIdx.x;
    if (i >= BB) return;
    int im = (int)x[(size_t)i * LD_X + 1796];
    atomicAdd(&g_cnt[im], 1);
}
__global__ void prefix_kernel() {
    if (blockIdx.x == 0 && threadIdx.x == 0) {
        int s = 0;
        for (int i = 0; i < NIMG; i++) { g_off[i] = s; s += g_cnt[i]; }
        g_off[NIMG] = s;
    }
}
__global__ void fill_kernel(const float* __restrict__ x) {
    int i = blockIdx.x * blockDim.x + threadIdx.x;
    if (i >= BB) return;
    int im = (int)x[(size_t)i * LD_X + 1796];
    int p = atomicAdd(&g_cur[im], 1);
    g_bucket[g_off[im] + p] = i;
}

__device__ __forceinline__ void topk_insert(float* val, int* ind, float s, int j) {
    if (s > val[KNN - 1]) {
        int p = KNN - 1;
        while (p > 0 && s > val[p - 1]) { val[p] = val[p - 1]; ind[p] = ind[p - 1]; p--; }
        val[p] = s; ind[p] = j;
    }
}

__global__ void knn_topk_kernel(const float* __restrict__ x)
{
    int i = blockIdx.x * blockDim.x + threadIdx.x;
    if (i >= BB) return;
    const float* xi = x + (size_t)i * LD_X;
    float cx = xi[1792], cy = xi[1793];
    int im = (int)xi[1796];
    float sqi = cx * cx + cy * cy;

    float val[KNN]; int ind[KNN];
    #pragma unroll
    for (int k = 0; k < KNN; k++) { val[k] = NEGV; ind[k] = 0; }

    int s = g_off[im], e = g_off[im + 1];
    int m = 0;
    for (int p = s; p < e; p++) {
        int j = g_bucket[p];
        if (j == i) continue;
        const float* xj = x + (size_t)j * LD_X;
        float jx = xj[1792], jy = xj[1793];
        float sqj = jx * jx + jy * jy;
        float d2 = sqi + sqj - 2.f * (cx * jx + cy * jy);
        float sim = -sqrtf(fmaxf(d2, 0.f));
        m++;
        topk_insert(val, ind, sim, j);
    }
    if (m == 0) {
        for (int j = 0; j < BB; j++) {
            if (j == i) continue;
            const float* xj = x + (size_t)j * LD_X;
            float jx = xj[1792], jy = xj[1793];
            float sqj = jx * jx + jy * jy;
            float d2 = sqi + sqj - 2.f * (cx * jx + cy * jy);
            float sim = -sqrtf(fmaxf(d2, 0.f));
            topk_insert(val, ind, sim, j);
        }
    }
    float mx = val[0];
    float w[KNN], sum = 0.f;
    #pragma unroll
    for (int k = 0; k < KNN; k++) { w[k] = expf(val[k] - mx); sum += w[k]; }
    float inv = 1.f / sum;
    #pragma unroll
    for (int k = 0; k < KNN; k++) {
        g_w[(size_t)i * KNN + k] = w[k] * inv;
        g_nidx[(size_t)i * KNN + k] = ind[k];
    }
}

// ---------------- weighted gather: out[i,:] = sum_k w[i,k] * F[idx[i,k],:] ----------------
__global__ void gather_kernel(const float* __restrict__ F, float* __restrict__ out)
{
    int row = blockIdx.x;
    __shared__ float sw[KNN];
    __shared__ int   si[KNN];
    if (threadIdx.x < KNN) {
        sw[threadIdx.x] = g_w[(size_t)row * KNN + threadIdx.x];
        si[threadIdx.x] = g_nidx[(size_t)row * KNN + threadIdx.x];
    }
    __syncthreads();
    for (int c = threadIdx.x; c < FDIM; c += blockDim.x) {
        float acc = 0.f;
        #pragma unroll
        for (int k = 0; k < KNN; k++) acc += sw[k] * F[(size_t)si[k] * FDIM + c];
        out[(size_t)row * FDIM + c] = acc;
    }
}

// ---------------- gate_in concat ----------------
__global__ void gin_kernel()
{
    int t = blockIdx.x * blockDim.x + threadIdx.x;
    if (t >= BB * GI) return;
    int row = t / GI, c = t % GI;
    float v;
    if (c < FDIM)           v = g_base[(size_t)row * FDIM + c];
    else if (c < FDIM + CC) v = g_cp[(size_t)row * CC + (c - FDIM)];
    else                    v = g_tok[(size_t)row * HH + (c - FDIM - CC)];
    g_gin[t] = v;
}

// ---------------- gate second layer + softmax + entropy ----------------
__global__ void gate2_kernel(const float* __restrict__ Wg2, const float* __restrict__ bg2)
{
    int warp = threadIdx.x >> 5, lane = threadIdx.x & 31;
    int row = blockIdx.x * 8 + warp;
    if (row >= BB) return;
    float a0 = 0.f, a1 = 0.f;
    const float* h = g_hid + (size_t)row * GHH;
    for (int k = lane; k < GHH; k += 32) {
        float hv = h[k];
        a0 += hv * Wg2[k * 2];
        a1 += hv * Wg2[k * 2 + 1];
    }
    for (int o = 16; o; o >>= 1) {
        a0 += __shfl_xor_sync(0xffffffff, a0, o);
        a1 += __shfl_xor_sync(0xffffffff, a1, o);
    }
    if (lane == 0) {
        float z0 = a0 + bg2[0], z1 = a1 + bg2[1];
        float mx = fmaxf(z0, z1);
        float e0 = expf(z0 - mx), e1 = expf(z1 - mx);
        float sinv = 1.f / (e0 + e1);
        float p0 = e0 * sinv, p1 = e1 * sinv;
        g_gp[(size_t)row * 2] = p0;
        g_gp[(size_t)row * 2 + 1] = p1;
        g_ent[row] = -(p0 * logf(p0 + 1e-8f) + p1 * logf(p1 + 1e-8f));
    }
}

// ---------------- fused = [fv*g0, ft*g1] ----------------
__global__ void fmul_kernel()
{
    int t = blockIdx.x * blockDim.x + threadIdx.x;
    if (t >= BB * FDIM) return;
    int row = t >> 9, c = t & 511;
    g_fused[t] = g_base[t] * g_gp[(size_t)row * 2 + (c >= HH ? 1 : 0)];
}

// ---------------- final classifier layer 2 -> logits ----------------
__global__ void c2_kernel(const float* __restrict__ Wc2, const float* __restrict__ bc2,
                          float* __restrict__ out)
{
    int warp = threadIdx.x >> 5, lane = threadIdx.x & 31;
    int row = blockIdx.x * 8 + warp;
    if (row >= BB) return;
    const float* h = g_h + (size_t)row * HH;
    float acc[CC] = {0, 0, 0, 0, 0};
    for (int k = lane; k < HH; k += 32) {
        float hv = h[k];
        #pragma unroll
        for (int c = 0; c < CC; c++) acc[c] += hv * Wc2[k * CC + c];
    }
    #pragma unroll
    for (int c = 0; c < CC; c++)
        for (int o = 16; o; o >>= 1) acc[c] += __shfl_xor_sync(0xffffffff, acc[c], o);
    if (lane == 0) {
        #pragma unroll
        for (int c = 0; c < CC; c++) out[(size_t)row * CC + c] = acc[c] + bc2[c];
    }
}

// ---------------- entropy mean (deterministic tree reduce) ----------------
__global__ void ent_reduce_kernel(float* __restrict__ out)
{
    __shared__ float red[256];
    int tid = threadIdx.x;
    float s = 0.f;
    for (int t = tid; t < BB; t += 256) s += g_ent[t];
    red[tid] = s; __syncthreads();
    for (int o = 128; o > 0; o >>= 1) { if (tid < o) red[tid] += red[tid + o]; __syncthreads(); }
    if (tid == 0) out[0] = red[0] / (float)BB * 0.01f;
}

// ---------------- launch ----------------
static float* sym_f(const void* p) { return (float*)p; }

extern "C" void kernel_launch(void* const* d_in, const int* in_sizes, int n_in,
                              void* d_out, int out_size)
{
    const float* x     = (const float*)d_in[0];
    const float* ln_vg = (const float*)d_in[1];
    const float* ln_vb = (const float*)d_in[2];
    const float* ln_tg = (const float*)d_in[3];
    const float* ln_tb = (const float*)d_in[4];
    const float* W_v   = (const float*)d_in[5];
    const float* b_v   = (const float*)d_in[6];
    const float* W_t   = (const float*)d_in[7];
    const float* b_t   = (const float*)d_in[8];
    const float* W_cp  = (const float*)d_in[9];
    const float* b_cp  = (const float*)d_in[10];
    const float* W_ctx1 = (const float*)d_in[11];
    const float* b_ctx1 = (const float*)d_in[12];
    const float* W_ctx2 = (const float*)d_in[13];
    const float* b_ctx2 = (const float*)d_in[14];
    const float* W_g1  = (const float*)d_in[15];
    const float* b_g1  = (const float*)d_in[16];
    const float* W_g2  = (const float*)d_in[17];
    const float* b_g2  = (const float*)d_in[18];
    const float* W_gu1 = (const float*)d_in[19];
    const float* b_gu1 = (const float*)d_in[20];
    const float* W_gu2 = (const float*)d_in[21];
    const float* b_gu2 = (const float*)d_in[22];
    const float* W_c1  = (const float*)d_in[23];
    const float* b_c1  = (const float*)d_in[24];
    const float* bn_g  = (const float*)d_in[25];
    const float* bn_b  = (const float*)d_in[26];
    const float* W_c2  = (const float*)d_in[27];
    const float* b_c2  = (const float*)d_in[28];
    float* out = (float*)d_out;

    void *p_xn, *p_base, *p_agg, *p_t1, *p_tok, *p_gin, *p_hid, *p_fused, *p_u1, *p_h;
    cudaGetSymbolAddress(&p_xn, g_xn);
    cudaGetSymbolAddress(&p_base, g_base);
    cudaGetSymbolAddress(&p_agg, g_agg);
    cudaGetSymbolAddress(&p_t1, g_t1);
    cudaGetSymbolAddress(&p_tok, g_tok);
    cudaGetSymbolAddress(&p_gin, g_gin);
    cudaGetSymbolAddress(&p_hid, g_hid);
    cudaGetSymbolAddress(&p_fused, g_fused);
    cudaGetSymbolAddress(&p_u1, g_u1);
    cudaGetSymbolAddress(&p_h, g_h);
    float* xn    = sym_f(p_xn);
    float* base  = sym_f(p_base);
    float* agg   = sym_f(p_agg);
    float* t1    = sym_f(p_t1);
    float* tok   = sym_f(p_tok);
    float* gin   = sym_f(p_gin);
    float* hid   = sym_f(p_hid);
    float* fused = sym_f(p_fused);
    float* u1    = sym_f(p_u1);
    float* hbuf  = sym_f(p_h);

    // 1) LayerNorm both segments
    ln_kernel<<<BB, 256>>>(x, ln_vg, ln_vb, ln_tg, ln_tb);

    // 2) fv / ft GEMMs -> base_fused columns
    dim3 gA(HH / 128, BB / 128);   // (2, 64)
    gemm_mma<E_BIAS><<<gA, 256>>>(xn, 1792, W_v, b_v, base, FDIM, HH, DV,
                                  nullptr, nullptr, nullptr, 0, 0.f);
    gemm_mma<E_BIAS><<<gA, 256>>>(xn + DV, 1792, W_t, b_t, base + HH, FDIM, HH, DT,
                                  nullptr, nullptr, nullptr, 0, 0.f);

    // 3) class prior
    cp_kernel<<<BB / 8, 256>>>(W_cp, b_cp);

    // 4) KNN (shared between both aggregates)
    zero_cnt_kernel<<<2, 256>>>();
    count_kernel<<<BB / 256, 256>>>(x);
    prefix_kernel<<<1, 32>>>();
    fill_kernel<<<BB / 256, 256>>>(x);
    knn_topk_kernel<<<BB / 256, 256>>>(x);

    // 5) neigh_agg over base_fused -> spatial_token
    gather_kernel<<<BB, 128>>>(base, agg);
    gemm_mma<E_RELU><<<gA, 256>>>(agg, FDIM, W_ctx1, b_ctx1, t1, HH, HH, FDIM,
                                  nullptr, nullptr, nullptr, 0, 0.f);
    gemm_mma<E_BIAS><<<gA, 256>>>(t1, HH, W_ctx2, b_ctx2, tok, HH, HH, HH,
                                  nullptr, nullptr, nullptr, 0, 0.f);

    // 6) gate
    gin_kernel<<<(BB * GI + 255) / 256, 256>>>();
    dim3 gG(GHH / 128, BB / 128);  // (1, 64)
    gemm_mma<E_RELU><<<gG, 256>>>(gin, GI, W_g1, b_g1, hid, GHH, GHH, GI,
                                  nullptr, nullptr, nullptr, 0, 0.f);
    gate2_kernel<<<BB / 8, 256>>>(W_g2, b_g2);

    // 7) fused = gated base, spatial update, residual
    fmul_kernel<<<(BB * FDIM + 255) / 256, 256>>>();
    gather_kernel<<<BB, 128>>>(fused, agg);
    dim3 gF(FDIM / 128, BB / 128); // (4, 64)
    gemm_mma<E_RELU><<<gF, 256>>>(agg, FDIM, W_gu1, b_gu1, u1, FDIM, FDIM, FDIM,
                                  nullptr, nullptr, nullptr, 0, 0.f);
    gemm_mma<E_RESID><<<gF, 256>>>(u1, FDIM, W_gu2, b_gu2, fused, FDIM, FDIM, FDIM,
                                   nullptr, nullptr, fused, FDIM, 0.5f);

    // 8) classifier
    gemm_mma<E_BN><<<gA, 256>>>(fused, FDIM, W_c1, b_c1, hbuf, HH, HH, FDIM,
                                bn_g, bn_b, nullptr, 0, 0.f);
    c2_kernel<<<BB / 8, 256>>>(W_c2, b_c2, out);

    // 9) entropy scalar -> last output element
    ent_reduce_kernel<<<1, 256>>>(out + (out_size - 1));
}

// round 7
// speedup vs baseline: 2.3244x; 1.0306x over previous
#include <cuda_runtime.h>
#include <cuda_bf16.h>
#include <math.h>
#include <stdint.h>

// ---------------- problem constants ----------------
#define BB 8192
#define DV 1024
#define DT 768
#define LD_X 1797      // DV + DT + 4 + 1
#define HH 256
#define CC 5
#define GHH 128
#define KNN 8
#define FDIM 512       // 2*H
#define GI 773         // FD + C + H
#define NIMG 512
#define NEGV (-1000000000.0f)

// ---------------- scratch (device globals, allocation-free) ----------------
__device__ float g_xn[(size_t)BB * 1792];      // normalized [xv | xt]
__device__ float g_base[(size_t)BB * FDIM];    // base_fused
__device__ float g_cp[(size_t)BB * CC];        // class_prior
__device__ float g_agg[(size_t)BB * FDIM];     // knn aggregate (reused twice)
__device__ float g_t1[(size_t)BB * HH];        // ctx hidden
__device__ float g_tok[(size_t)BB * HH];       // spatial_token
__device__ float g_gin[(size_t)BB * GI];       // gate input concat
__device__ float g_hid[(size_t)BB * GHH];      // gate hidden
__device__ float g_gp[(size_t)BB * 2];         // gate probs
__device__ float g_ent[BB];                    // per-row entropy
__device__ float g_fused[(size_t)BB * FDIM];   // gated fused (updated in place)
__device__ float g_u1[(size_t)BB * FDIM];      // gu hidden
__device__ float g_h[(size_t)BB * HH];         // classifier hidden
__device__ float g_w[(size_t)BB * KNN];        // knn softmax weights
__device__ int   g_nidx[(size_t)BB * KNN];     // knn indices
__device__ int   g_cnt[NIMG];
__device__ int   g_off[NIMG + 1];
__device__ int   g_cur[NIMG];
__device__ int   g_bucket[BB];

// pre-split weight arenas: [N][K2] bf16, K2 = K padded to 32
#define WSZ 1413120
__device__ __align__(16) __nv_bfloat16 g_whi[WSZ];
__device__ __align__(16) __nv_bfloat16 g_wlo[WSZ];
// element offsets (K2 x N): v:1024x256 t:768x256 c1:512x256 c2:256x256
// g1:800x128 u1:512x512 u2:512x512 cl1:512x256
#define OW_V   0
#define OW_T   262144
#define OW_C1  458752
#define OW_C2  589824
#define OW_G1  655360
#define OW_U1  757760
#define OW_U2  1019904
#define OW_CL1 1282048

// ---------------- helpers ----------------
__device__ __forceinline__ uint32_t smem_u32(const void* p) {
    uint32_t a;
    asm("{ .reg .u64 t; cvta.to.shared.u64 t, %1; cvt.u32.u64 %0, t; }" : "=r"(a) : "l"(p));
    return a;
}
__device__ __forceinline__ void ldm_x4(uint32_t& r0, uint32_t& r1, uint32_t& r2, uint32_t& r3,
                                       uint32_t addr) {
    asm volatile("ldmatrix.sync.aligned.m8n8.x4.shared.b16 {%0,%1,%2,%3}, [%4];"
        : "=r"(r0), "=r"(r1), "=r"(r2), "=r"(r3) : "r"(addr));
}
__device__ __forceinline__ void mma16816(float* d, const uint32_t* a, uint32_t b0, uint32_t b1) {
    asm volatile(
        "mma.sync.aligned.m16n8k16.row.col.f32.bf16.bf16.f32 "
        "{%0,%1,%2,%3}, {%4,%5,%6,%7}, {%8,%9}, {%0,%1,%2,%3};"
        : "+f"(d[0]), "+f"(d[1]), "+f"(d[2]), "+f"(d[3])
        : "r"(a[0]), "r"(a[1]), "r"(a[2]), "r"(a[3]), "r"(b0), "r"(b1));
}
__device__ __forceinline__ void split2(float x, float y, uint32_t& hi, uint32_t& lo) {
    __nv_bfloat162 h = __floats2bfloat162_rn(x, y);     // x -> low half
    float xr = x - __bfloat162float(__low2bfloat16(h));
    float yr = y - __bfloat162float(__high2bfloat16(h));
    __nv_bfloat162 l = __floats2bfloat162_rn(xr, yr);
    hi = *(uint32_t*)&h;
    lo = *(uint32_t*)&l;
}

// ---------------- weight transpose+split: W[K][N] fp32 -> hi/lo [N][K2] bf16 ----------------
__global__ void wsplit_kernel(const float* __restrict__ W, int K, int N, int K2,
                              __nv_bfloat16* __restrict__ hi, __nv_bfloat16* __restrict__ lo)
{
    __shared__ float tile[32][33];
    int kt = blockIdx.x * 32, nt = blockIdx.y * 32;
    int tx = threadIdx.x, ty = threadIdx.y;   // 32 x 8
    #pragma unroll
    for (int i = 0; i < 4; i++) {
        int k = kt + ty + i * 8;
        tile[ty + i * 8][tx] = (k < K) ? W[(size_t)k * N + nt + tx] : 0.f;
    }
    __syncthreads();
    #pragma unroll
    for (int i = 0; i < 4; i++) {
        int n = nt + ty + i * 8;
        int k = kt + tx;
        float v = tile[tx][ty + i * 8];
        __nv_bfloat16 h = __float2bfloat16_rn(v);
        __nv_bfloat16 l = __float2bfloat16_rn(v - __bfloat162float(h));
        hi[(size_t)n * K2 + k] = h;
        lo[(size_t)n * K2 + k] = l;
    }
}

// ---------------- LayerNorm (per-row, fused for v and t segments) ----------------
__global__ void ln_kernel(const float* __restrict__ x,
                          const float* __restrict__ gv, const float* __restrict__ bv,
                          const float* __restrict__ gt, const float* __restrict__ bt)
{
    int row = blockIdx.x;
    const float* xr = x + (size_t)row * LD_X;
    float* outr = g_xn + (size_t)row * 1792;
    __shared__ float red[256];
    int tid = threadIdx.x;

    float s = 0.f;
    for (int c = tid; c < DV; c += 256) s += xr[c];
    red[tid] = s; __syncthreads();
    for (int o = 128; o > 0; o >>= 1) { if (tid < o) red[tid] += red[tid + o]; __syncthreads(); }
    float m = red[0] / (float)DV;
    __syncthreads();
    float s2 = 0.f;
    for (int c = tid; c < DV; c += 256) { float d = xr[c] - m; s2 += d * d; }
    red[tid] = s2; __syncthreads();
    for (int o = 128; o > 0; o >>= 1) { if (tid < o) red[tid] += red[tid + o]; __syncthreads(); }
    float r = rsqrtf(red[0] / (float)DV + 1e-5f);
    __syncthreads();
    for (int c = tid; c < DV; c += 256) outr[c] = (xr[c] - m) * r * gv[c] + bv[c];

    s = 0.f;
    for (int c = tid; c < DT; c += 256) s += xr[DV + c];
    red[tid] = s; __syncthreads();
    for (int o = 128; o > 0; o >>= 1) { if (tid < o) red[tid] += red[tid + o]; __syncthreads(); }
    m = red[0] / (float)DT;
    __syncthreads();
    s2 = 0.f;
    for (int c = tid; c < DT; c += 256) { float d = xr[DV + c] - m; s2 += d * d; }
    red[tid] = s2; __syncthreads();
    for (int o = 128; o > 0; o >>= 1) { if (tid < o) red[tid] += red[tid + o]; __syncthreads(); }
    r = rsqrtf(red[0] / (float)DT + 1e-5f);
    __syncthreads();
    for (int c = tid; c < DT; c += 256) outr[DV + c] = (xr[DV + c] - m) * r * gt[c] + bt[c];
}

// ---------------- 3xBF16 mma.sync GEMM (ldmatrix + pre-split weights) ----------------
// CTA 128x128, 256 threads (8 warps as 4m x 2n), warp tile 32m x 64n.
// A fp32 [M][K] split in-kernel; B pre-split bf16 [N][K2] hi/lo.
#define E_BIAS  0
#define E_RELU  1
#define E_RESID 2
#define E_BN    3
#define SRW 20   // smem row stride in 32-bit words

template<int EPI>
__global__ void __launch_bounds__(256)
gemm_mma(const float* __restrict__ A, int lda,
         const __nv_bfloat16* __restrict__ Whi,   // [N][K2]
         const __nv_bfloat16* __restrict__ Wlo,
         int K2,
         const float* __restrict__ bias,
         float* __restrict__ C, int ldc,
         int N, int K,
         const float* __restrict__ scale, const float* __restrict__ shift,
         const float* __restrict__ resid, int ldr, float alpha)
{
    __shared__ uint32_t sAhi[128 * SRW], sAlo[128 * SRW];
    __shared__ uint32_t sBhi[128 * SRW], sBlo[128 * SRW];

    int tid = threadIdx.x;
    int lane = tid & 31, wid = tid >> 5;
    int bm = blockIdx.y * 128, bn = blockIdx.x * 128;
    int wm = (wid >> 1) * 32, wn = (wid & 1) * 64;

    float acc[2][8][4];
    #pragma unroll
    for (int mf = 0; mf < 2; mf++)
        #pragma unroll
        for (int nf = 0; nf < 8; nf++)
            #pragma unroll
            for (int q = 0; q < 4; q++) acc[mf][nf][q] = 0.f;

    // A staging: row = tid>>3 (+32 per pass), kq = (tid&7)*4
    int a_r = tid >> 3, a_kq = (tid & 7) * 4;
    // B staging: n = tid&127, kb = (tid>>7)*16 (16 bf16 = 2 x uint4)
    int b_n = tid & 127, b_kb = (tid >> 7) * 16;

    float aReg[4][4];
    uint4 bh4[2], bl4[2];

    int nch = (K + 31) / 32;
    const bool avec = ((lda & 3) == 0) && ((K & 31) == 0);

    // ldmatrix lane geometry
    uint32_t pAhi = smem_u32(sAhi), pAlo = smem_u32(sAlo);
    uint32_t pBhi = smem_u32(sBhi), pBlo = smem_u32(sBlo);
    int aRow = wm + (lane & 7) + ((lane >> 3) & 1) * 8;   // + mf*16
    int aKw  = ((lane >> 4) & 1) * 4;                      // + ks*8
    int bRow = wn + (lane & 7) + ((lane >> 4) & 1) * 8;   // + np*16
    int bKw  = ((lane >> 3) & 1) * 4;                      // + ks*8

    // ---- preload chunk 0 ----
    {
        if (avec) {
            #pragma unroll
            for (int p = 0; p < 4; p++)
                *(float4*)aReg[p] = *(const float4*)&A[(size_t)(bm + a_r + p * 32) * lda + a_kq];
        } else {
            #pragma unroll
            for (int p = 0; p < 4; p++)
                #pragma unroll
                for (int q = 0; q < 4; q++) {
                    int kk = a_kq + q;
                    aReg[p][q] = (kk < K) ? A[(size_t)(bm + a_r + p * 32) * lda + kk] : 0.f;
                }
        }
        const uint4* ph = (const uint4*)(Whi + (size_t)(bn + b_n) * K2 + b_kb);
        const uint4* pl = (const uint4*)(Wlo + (size_t)(bn + b_n) * K2 + b_kb);
        bh4[0] = ph[0]; bh4[1] = ph[1];
        bl4[0] = pl[0]; bl4[1] = pl[1];
    }

    for (int ch = 0; ch < nch; ch++) {
        __syncthreads();   // previous compute done reading smem
        // ---- STS ----
        #pragma unroll
        for (int p = 0; p < 4; p++) {
            uint32_t h0, l0, h1, l1;
            split2(aReg[p][0], aReg[p][1], h0, l0);
            split2(aReg[p][2], aReg[p][3], h1, l1);
            int idx = (a_r + p * 32) * SRW + (a_kq >> 1);
            *(uint2*)&sAhi[idx] = make_uint2(h0, h1);
            *(uint2*)&sAlo[idx] = make_uint2(l0, l1);
        }
        {
            int idx = b_n * SRW + (b_kb >> 1);
            *(uint4*)&sBhi[idx]     = bh4[0];
            *(uint4*)&sBhi[idx + 4] = bh4[1];
            *(uint4*)&sBlo[idx]     = bl4[0];
            *(uint4*)&sBlo[idx + 4] = bl4[1];
        }
        __syncthreads();

        // ---- prefetch next chunk ----
        if (ch + 1 < nch) {
            int k0 = (ch + 1) * 32;
            if (avec) {
                #pragma unroll
                for (int p = 0; p < 4; p++)
                    *(float4*)aReg[p] = *(const float4*)&A[(size_t)(bm + a_r + p * 32) * lda + k0 + a_kq];
            } else {
                #pragma unroll
                for (int p = 0; p < 4; p++)
                    #pragma unroll
                    for (int q = 0; q < 4; q++) {
                        int kk = k0 + a_kq + q;
                        aReg[p][q] = (kk < K) ? A[(size_t)(bm + a_r + p * 32) * lda + kk] : 0.f;
                    }
            }
            const uint4* ph = (const uint4*)(Whi + (size_t)(bn + b_n) * K2 + k0 + b_kb);
            const uint4* pl = (const uint4*)(Wlo + (size_t)(bn + b_n) * K2 + k0 + b_kb);
            bh4[0] = ph[0]; bh4[1] = ph[1];
            bl4[0] = pl[0]; bl4[1] = pl[1];
        }

        // ---- compute: 2 k16-steps via ldmatrix ----
        #pragma unroll
        for (int ks = 0; ks < 2; ks++) {
            uint32_t ah[2][4], al[2][4];
            #pragma unroll
            for (int mf = 0; mf < 2; mf++) {
                uint32_t off = (uint32_t)((aRow + mf * 16) * SRW + ks * 8 + aKw) * 4u;
                ldm_x4(ah[mf][0], ah[mf][1], ah[mf][2], ah[mf][3], pAhi + off);
                ldm_x4(al[mf][0], al[mf][1], al[mf][2], al[mf][3], pAlo + off);
            }
            uint32_t bh[8][2], bl[8][2];
            #pragma unroll
            for (int np = 0; np < 4; np++) {
                uint32_t off = (uint32_t)((bRow + np * 16) * SRW + ks * 8 + bKw) * 4u;
                ldm_x4(bh[2 * np][0], bh[2 * np][1], bh[2 * np + 1][0], bh[2 * np + 1][1], pBhi + off);
                ldm_x4(bl[2 * np][0], bl[2 * np][1], bl[2 * np + 1][0], bl[2 * np + 1][1], pBlo + off);
            }
            #pragma unroll
            for (int nf = 0; nf < 8; nf++) {
                #pragma unroll
                for (int mf = 0; mf < 2; mf++) {
                    mma16816(acc[mf][nf], ah[mf], bh[nf][0], bh[nf][1]);
                    mma16816(acc[mf][nf], ah[mf], bl[nf][0], bl[nf][1]);
                    mma16816(acc[mf][nf], al[mf], bh[nf][0], bh[nf][1]);
                }
            }
        }
    }

    // ---- epilogue ----
    int mb = bm + wm + (lane >> 2);
    int nb = bn + wn + 2 * (lane & 3);
    #pragma unroll
    for (int mf = 0; mf < 2; mf++) {
        #pragma unroll
        for (int nf = 0; nf < 8; nf++) {
            int n0 = nb + nf * 8;
            #pragma unroll
            for (int half = 0; half < 2; half++) {   // rows r, r+8
                int m = mb + mf * 16 + half * 8;
                float v0 = acc[mf][nf][half * 2 + 0] + bias[n0];
                float v1 = acc[mf][nf][half * 2 + 1] + bias[n0 + 1];
                if (EPI == E_RELU) { v0 = fmaxf(v0, 0.f); v1 = fmaxf(v1, 0.f); }
                else if (EPI == E_RESID) {
                    v0 = resid[(size_t)m * ldr + n0] + alpha * v0;
                    v1 = resid[(size_t)m * ldr + n0 + 1] + alpha * v1;
                }
                else if (EPI == E_BN) {
                    float rs = rsqrtf(1.f + 1e-5f);
                    v0 = fmaxf(v0 * (scale[n0] * rs) + shift[n0], 0.f);
                    v1 = fmaxf(v1 * (scale[n0 + 1] * rs) + shift[n0 + 1], 0.f);
                }
                *(float2*)&C[(size_t)m * ldc + n0] = make_float2(v0, v1);
            }
        }
    }
}

// ---------------- class_prior: softmax(base @ W_cp + b_cp), warp per row ----------------
__global__ void cp_kernel(const float* __restrict__ Wcp, const float* __restrict__ bcp)
{
    int warp = threadIdx.x >> 5, lane = threadIdx.x & 31;
    int row = blockIdx.x * 8 + warp;
    if (row >= BB) return;
    const float* f = g_base + (size_t)row * FDIM;
    float acc[CC] = {0, 0, 0, 0, 0};
    for (int k = lane; k < FDIM; k += 32) {
        float fv = f[k];
        #pragma unroll
        for (int c = 0; c < CC; c++) acc[c] += fv * Wcp[k * CC + c];
    }
    #pragma unroll
    for (int c = 0; c < CC; c++)
        for (int o = 16; o; o >>= 1) acc[c] += __shfl_xor_sync(0xffffffff, acc[c], o);
    if (lane == 0) {
        float z[CC], mx = -1e30f, sum = 0.f;
        #pragma unroll
        for (int c = 0; c < CC; c++) { z[c] = acc[c] + bcp[c]; mx = fmaxf(mx, z[c]); }
        #pragma unroll
        for (int c = 0; c < CC; c++) { z[c] = expf(z[c] - mx); sum += z[c]; }
        #pragma unroll
        for (int c = 0; c < CC; c++) g_cp[(size_t)row * CC + c] = z[c] / sum;
    }
}

// ---------------- KNN: bucket by image, per-point top-8 ----------------
__global__ void zero_cnt_kernel() {
    int t = blockIdx.x * blockDim.x + threadIdx.x;
    if (t < NIMG) { g_cnt[t] = 0; g_cur[t] = 0; }
}
__global__ void count_kernel(const float* __restrict__ x) {
    int i = blockIdx.x * blockDim.x + threadIdx.x;
    if (i >= BB) return;
    int im = (int)x[(size_t)i * LD_X + 1796];
    atomicAdd(&g_cnt[im], 1);
}
__global__ void prefix_kernel() {
    if (blockIdx.x == 0 && threadIdx.x == 0) {
        int s = 0;
        for (int i = 0; i < NIMG; i++) { g_off[i] = s; s += g_cnt[i]; }
        g_off[NIMG] = s;
    }
}
__global__ void fill_kernel(const float* __restrict__ x) {
    int i = blockIdx.x * blockDim.x + threadIdx.x;
    if (i >= BB) return;
    int im = (int)x[(size_t)i * LD_X + 1796];
    int p = atomicAdd(&g_cur[im], 1);
    g_bucket[g_off[im] + p] = i;
}

__device__ __forceinline__ void topk_insert(float* val, int* ind, float s, int j) {
    if (s > val[KNN - 1]) {
        int p = KNN - 1;
        while (p > 0 && s > val[p - 1]) { val[p] = val[p - 1]; ind[p] = ind[p - 1]; p--; }
        val[p] = s; ind[p] = j;
    }
}

__global__ void knn_topk_kernel(const float* __restrict__ x)
{
    int i = blockIdx.x * blockDim.x + threadIdx.x;
    if (i >= BB) return;
    const float* xi = x + (size_t)i * LD_X;
    float cx = xi[1792], cy = xi[1793];
    int im = (int)xi[1796];
    float sqi = cx * cx + cy * cy;

    float val[KNN]; int ind[KNN];
    #pragma unroll
    for (int k = 0; k < KNN; k++) { val[k] = NEGV; ind[k] = 0; }

    int s = g_off[im], e = g_off[im + 1];
    int m = 0;
    for (int p = s; p < e; p++) {
        int j = g_bucket[p];
        if (j == i) continue;
        const float* xj = x + (size_t)j * LD_X;
        float jx = xj[1792], jy = xj[1793];
        float sqj = jx * jx + jy * jy;
        float d2 = sqi + sqj - 2.f * (cx * jx + cy * jy);
        float sim = -sqrtf(fmaxf(d2, 0.f));
        m++;
        topk_insert(val, ind, sim, j);
    }
    if (m == 0) {
        for (int j = 0; j < BB; j++) {
            if (j == i) continue;
            const float* xj = x + (size_t)j * LD_X;
            float jx = xj[1792], jy = xj[1793];
            float sqj = jx * jx + jy * jy;
            float d2 = sqi + sqj - 2.f * (cx * jx + cy * jy);
            float sim = -sqrtf(fmaxf(d2, 0.f));
            topk_insert(val, ind, sim, j);
        }
    }
    float mx = val[0];
    float w[KNN], sum = 0.f;
    #pragma unroll
    for (int k = 0; k < KNN; k++) { w[k] = expf(val[k] - mx); sum += w[k]; }
    float inv = 1.f / sum;
    #pragma unroll
    for (int k = 0; k < KNN; k++) {
        g_w[(size_t)i * KNN + k] = w[k] * inv;
        g_nidx[(size_t)i * KNN + k] = ind[k];
    }
}

// ---------------- weighted gather: out[i,:] = sum_k w[i,k] * F[idx[i,k],:] ----------------
__global__ void gather_kernel(const float* __restrict__ F, float* __restrict__ out)
{
    int row = blockIdx.x;
    __shared__ float sw[KNN];
    __shared__ int   si[KNN];
    if (threadIdx.x < KNN) {
        sw[threadIdx.x] = g_w[(size_t)row * KNN + threadIdx.x];
        si[threadIdx.x] = g_nidx[(size_t)row * KNN + threadIdx.x];
    }
    __syncthreads();
    for (int c = threadIdx.x; c < FDIM; c += blockDim.x) {
        float acc = 0.f;
        #pragma unroll
        for (int k = 0; k < KNN; k++) acc += sw[k] * F[(size_t)si[k] * FDIM + c];
        out[(size_t)row * FDIM + c] = acc;
    }
}

// ---------------- gate_in concat ----------------
__global__ void gin_kernel()
{
    int t = blockIdx.x * blockDim.x + threadIdx.x;
    if (t >= BB * GI) return;
    int row = t / GI, c = t % GI;
    float v;
    if (c < FDIM)           v = g_base[(size_t)row * FDIM + c];
    else if (c < FDIM + CC) v = g_cp[(size_t)row * CC + (c - FDIM)];
    else                    v = g_tok[(size_t)row * HH + (c - FDIM - CC)];
    g_gin[t] = v;
}

// ---------------- gate second layer + softmax + entropy ----------------
__global__ void gate2_kernel(const float* __restrict__ Wg2, const float* __restrict__ bg2)
{
    int warp = threadIdx.x >> 5, lane = threadIdx.x & 31;
    int row = blockIdx.x * 8 + warp;
    if (row >= BB) return;
    float a0 = 0.f, a1 = 0.f;
    const float* h = g_hid + (size_t)row * GHH;
    for (int k = lane; k < GHH; k += 32) {
        float hv = h[k];
        a0 += hv * Wg2[k * 2];
        a1 += hv * Wg2[k * 2 + 1];
    }
    for (int o = 16; o; o >>= 1) {
        a0 += __shfl_xor_sync(0xffffffff, a0, o);
        a1 += __shfl_xor_sync(0xffffffff, a1, o);
    }
    if (lane == 0) {
        float z0 = a0 + bg2[0], z1 = a1 + bg2[1];
        float mx = fmaxf(z0, z1);
        float e0 = expf(z0 - mx), e1 = expf(z1 - mx);
        float sinv = 1.f / (e0 + e1);
        float p0 = e0 * sinv, p1 = e1 * sinv;
        g_gp[(size_t)row * 2] = p0;
        g_gp[(size_t)row * 2 + 1] = p1;
        g_ent[row] = -(p0 * logf(p0 + 1e-8f) + p1 * logf(p1 + 1e-8f));
    }
}

// ---------------- fused = [fv*g0, ft*g1] ----------------
__global__ void fmul_kernel()
{
    int t = blockIdx.x * blockDim.x + threadIdx.x;
    if (t >= BB * FDIM) return;
    int row = t >> 9, c = t & 511;
    g_fused[t] = g_base[t] * g_gp[(size_t)row * 2 + (c >= HH ? 1 : 0)];
}

// ---------------- final classifier layer 2 -> logits ----------------
__global__ void c2_kernel(const float* __restrict__ Wc2, const float* __restrict__ bc2,
                          float* __restrict__ out)
{
    int warp = threadIdx.x >> 5, lane = threadIdx.x & 31;
    int row = blockIdx.x * 8 + warp;
    if (row >= BB) return;
    const float* h = g_h + (size_t)row * HH;
    float acc[CC] = {0, 0, 0, 0, 0};
    for (int k = lane; k < HH; k += 32) {
        float hv = h[k];
        #pragma unroll
        for (int c = 0; c < CC; c++) acc[c] += hv * Wc2[k * CC + c];
    }
    #pragma unroll
    for (int c = 0; c < CC; c++)
        for (int o = 16; o; o >>= 1) acc[c] += __shfl_xor_sync(0xffffffff, acc[c], o);
    if (lane == 0) {
        #pragma unroll
        for (int c = 0; c < CC; c++) out[(size_t)row * CC + c] = acc[c] + bc2[c];
    }
}

// ---------------- entropy mean (deterministic tree reduce) ----------------
__global__ void ent_reduce_kernel(float* __restrict__ out)
{
    __shared__ float red[256];
    int tid = threadIdx.x;
    float s = 0.f;
    for (int t = tid; t < BB; t += 256) s += g_ent[t];
    red[tid] = s; __syncthreads();
    for (int o = 128; o > 0; o >>= 1) { if (tid < o) red[tid] += red[tid + o]; __syncthreads(); }
    if (tid == 0) out[0] = red[0] / (float)BB * 0.01f;
}

// ---------------- launch ----------------
static float* sym_f(const void* p) { return (float*)p; }

extern "C" void kernel_launch(void* const* d_in, const int* in_sizes, int n_in,
                              void* d_out, int out_size)
{
    const float* x     = (const float*)d_in[0];
    const float* ln_vg = (const float*)d_in[1];
    const float* ln_vb = (const float*)d_in[2];
    const float* ln_tg = (const float*)d_in[3];
    const float* ln_tb = (const float*)d_in[4];
    const float* W_v   = (const float*)d_in[5];
    const float* b_v   = (const float*)d_in[6];
    const float* W_t   = (const float*)d_in[7];
    const float* b_t   = (const float*)d_in[8];
    const float* W_cp  = (const float*)d_in[9];
    const float* b_cp  = (const float*)d_in[10];
    const float* W_ctx1 = (const float*)d_in[11];
    const float* b_ctx1 = (const float*)d_in[12];
    const float* W_ctx2 = (const float*)d_in[13];
    const float* b_ctx2 = (const float*)d_in[14];
    const float* W_g1  = (const float*)d_in[15];
    const float* b_g1  = (const float*)d_in[16];
    const float* W_g2  = (const float*)d_in[17];
    const float* b_g2  = (const float*)d_in[18];
    const float* W_gu1 = (const float*)d_in[19];
    const float* b_gu1 = (const float*)d_in[20];
    const float* W_gu2 = (const float*)d_in[21];
    const float* b_gu2 = (const float*)d_in[22];
    const float* W_c1  = (const float*)d_in[23];
    const float* b_c1  = (const float*)d_in[24];
    const float* bn_g  = (const float*)d_in[25];
    const float* bn_b  = (const float*)d_in[26];
    const float* W_c2  = (const float*)d_in[27];
    const float* b_c2  = (const float*)d_in[28];
    float* out = (float*)d_out;

    void *p_xn, *p_base, *p_agg, *p_t1, *p_tok, *p_gin, *p_hid, *p_fused, *p_u1, *p_h;
    void *p_whi, *p_wlo;
    cudaGetSymbolAddress(&p_xn, g_xn);
    cudaGetSymbolAddress(&p_base, g_base);
    cudaGetSymbolAddress(&p_agg, g_agg);
    cudaGetSymbolAddress(&p_t1, g_t1);
    cudaGetSymbolAddress(&p_tok, g_tok);
    cudaGetSymbolAddress(&p_gin, g_gin);
    cudaGetSymbolAddress(&p_hid, g_hid);
    cudaGetSymbolAddress(&p_fused, g_fused);
    cudaGetSymbolAddress(&p_u1, g_u1);
    cudaGetSymbolAddress(&p_h, g_h);
    cudaGetSymbolAddress(&p_whi, g_whi);
    cudaGetSymbolAddress(&p_wlo, g_wlo);
    float* xn    = sym_f(p_xn);
    float* base  = sym_f(p_base);
    float* agg   = sym_f(p_agg);
    float* t1    = sym_f(p_t1);
    float* tok   = sym_f(p_tok);
    float* gin   = sym_f(p_gin);
    float* hid   = sym_f(p_hid);
    float* fused = sym_f(p_fused);
    float* u1    = sym_f(p_u1);
    float* hbuf  = sym_f(p_h);
    __nv_bfloat16* whi = (__nv_bfloat16*)p_whi;
    __nv_bfloat16* wlo = (__nv_bfloat16*)p_wlo;

    dim3 wb(32, 8);
    // 0) pre-split weights (transpose to [N][K2] bf16 hi/lo)
    wsplit_kernel<<<dim3(1024/32, 256/32), wb>>>(W_v,   DV,  HH,  1024, whi + OW_V,   wlo + OW_V);
    wsplit_kernel<<<dim3(768/32,  256/32), wb>>>(W_t,   DT,  HH,  768,  whi + OW_T,   wlo + OW_T);
    wsplit_kernel<<<dim3(512/32,  256/32), wb>>>(W_ctx1,FDIM,HH,  512,  whi + OW_C1,  wlo + OW_C1);
    wsplit_kernel<<<dim3(256/32,  256/32), wb>>>(W_ctx2,HH,  HH,  256,  whi + OW_C2,  wlo + OW_C2);
    wsplit_kernel<<<dim3(800/32,  128/32), wb>>>(W_g1,  GI,  GHH, 800,  whi + OW_G1,  wlo + OW_G1);
    wsplit_kernel<<<dim3(512/32,  512/32), wb>>>(W_gu1, FDIM,FDIM,512,  whi + OW_U1,  wlo + OW_U1);
    wsplit_kernel<<<dim3(512/32,  512/32), wb>>>(W_gu2, FDIM,FDIM,512,  whi + OW_U2,  wlo + OW_U2);
    wsplit_kernel<<<dim3(512/32,  256/32), wb>>>(W_c1,  FDIM,HH,  512,  whi + OW_CL1, wlo + OW_CL1);

    // 1) LayerNorm both segments
    ln_kernel<<<BB, 256>>>(x, ln_vg, ln_vb, ln_tg, ln_tb);

    // 2) fv / ft GEMMs -> base_fused columns
    dim3 gA(HH / 128, BB / 128);   // (2, 64)
    gemm_mma<E_BIAS><<<gA, 256>>>(xn, 1792, whi + OW_V, wlo + OW_V, 1024, b_v, base, FDIM, HH, DV,
                                  nullptr, nullptr, nullptr, 0, 0.f);
    gemm_mma<E_BIAS><<<gA, 256>>>(xn + DV, 1792, whi + OW_T, wlo + OW_T, 768, b_t, base + HH, FDIM, HH, DT,
                                  nullptr, nullptr, nullptr, 0, 0.f);

    // 3) class prior
    cp_kernel<<<BB / 8, 256>>>(W_cp, b_cp);

    // 4) KNN (shared between both aggregates)
    zero_cnt_kernel<<<2, 256>>>();
    count_kernel<<<BB / 256, 256>>>(x);
    prefix_kernel<<<1, 32>>>();
    fill_kernel<<<BB / 256, 256>>>(x);
    knn_topk_kernel<<<BB / 256, 256>>>(x);

    // 5) neigh_agg over base_fused -> spatial_token
    gather_kernel<<<BB, 128>>>(base, agg);
    gemm_mma<E_RELU><<<gA, 256>>>(agg, FDIM, whi + OW_C1, wlo + OW_C1, 512, b_ctx1, t1, HH, HH, FDIM,
                                  nullptr, nullptr, nullptr, 0, 0.f);
    gemm_mma<E_BIAS><<<gA, 256>>>(t1, HH, whi + OW_C2, wlo + OW_C2, 256, b_ctx2, tok, HH, HH, HH,
                                  nullptr, nullptr, nullptr, 0, 0.f);

    // 6) gate
    gin_kernel<<<(BB * GI + 255) / 256, 256>>>();
    dim3 gG(GHH / 128, BB / 128);  // (1, 64)
    gemm_mma<E_RELU><<<gG, 256>>>(gin, GI, whi + OW_G1, wlo + OW_G1, 800, b_g1, hid, GHH, GHH, GI,
                                  nullptr, nullptr, nullptr, 0, 0.f);
    gate2_kernel<<<BB / 8, 256>>>(W_g2, b_g2);

    // 7) fused = gated base, spatial update, residual
    fmul_kernel<<<(BB * FDIM + 255) / 256, 256>>>();
    gather_kernel<<<BB, 128>>>(fused, agg);
    dim3 gF(FDIM / 128, BB / 128); // (4, 64)
    gemm_mma<E_RELU><<<gF, 256>>>(agg, FDIM, whi + OW_U1, wlo + OW_U1, 512, b_gu1, u1, FDIM, FDIM, FDIM,
                                  nullptr, nullptr, nullptr, 0, 0.f);
    gemm_mma<E_RESID><<<gF, 256>>>(u1, FDIM, whi + OW_U2, wlo + OW_U2, 512, b_gu2, fused, FDIM, FDIM, FDIM,
                                   nullptr, nullptr, fused, FDIM, 0.5f);

    // 8) classifier
    gemm_mma<E_BN><<<gA, 256>>>(fused, FDIM, whi + OW_CL1, wlo + OW_CL1, 512, b_c1, hbuf, HH, HH, FDIM,
                                bn_g, bn_b, nullptr, 0, 0.f);
    c2_kernel<<<BB / 8, 256>>>(W_c2, b_c2, out);

    // 9) entropy scalar -> last output element
    ent_reduce_kernel<<<1, 256>>>(out + (out_size - 1));
}

// round 10
// speedup vs baseline: 2.4006x; 1.0328x over previous
#include <cuda_runtime.h>
#include <cuda_bf16.h>
#include <math.h>
#include <stdint.h>

#define BB 8192
#define DV 1024
#define DT 768
#define LD_X 1797
#define HH 256
#define CC 5
#define GHH 128
#define KNN 8
#define FDIM 512
#define GI 773
#define NIMG 512
#define NEGV (-1000000000.0f)

__device__ float g_xn[(size_t)BB * 1792];
__device__ float g_base[(size_t)BB * FDIM];
__device__ float g_cp[(size_t)BB * CC];
__device__ float g_agg[(size_t)BB * FDIM];
__device__ float g_t1[(size_t)BB * HH];
__device__ float g_tok[(size_t)BB * HH];
__device__ float g_hid[(size_t)BB * GHH];
__device__ float g_gp[(size_t)BB * 2];
__device__ float g_ent[BB];
__device__ float g_fused[(size_t)BB * FDIM];
__device__ float g_u1[(size_t)BB * FDIM];
__device__ float g_h[(size_t)BB * HH];
__device__ float g_w[(size_t)BB * KNN];
__device__ int   g_nidx[(size_t)BB * KNN];
__device__ int   g_cnt[NIMG];
__device__ int   g_off[NIMG + 1];
__device__ int   g_cur[NIMG];
__device__ int   g_bucket[BB];

#define WSZ 1413120
__device__ __align__(16) __nv_bfloat16 g_whi[WSZ];
__device__ __align__(16) __nv_bfloat16 g_wlo[WSZ];
#define OW_V   0
#define OW_T   262144
#define OW_C1  458752
#define OW_C2  589824
#define OW_G1  655360
#define OW_U1  757760
#define OW_U2  1019904
#define OW_CL1 1282048

__device__ __forceinline__ uint32_t smem_u32(const void* p) {
    uint32_t a;
    asm("{ .reg .u64 t; cvta.to.shared.u64 t, %1; cvt.u32.u64 %0, t; }" : "=r"(a) : "l"(p));
    return a;
}
__device__ __forceinline__ void ldm_x4(uint32_t& r0, uint32_t& r1, uint32_t& r2, uint32_t& r3,
                                       uint32_t addr) {
    asm volatile("ldmatrix.sync.aligned.m8n8.x4.shared.b16 {%0,%1,%2,%3}, [%4];"
        : "=r"(r0), "=r"(r1), "=r"(r2), "=r"(r3) : "r"(addr));
}
__device__ __forceinline__ void mma16816(float* d, const uint32_t* a, uint32_t b0, uint32_t b1) {
    asm volatile(
        "mma.sync.aligned.m16n8k16.row.col.f32.bf16.bf16.f32 "
        "{%0,%1,%2,%3}, {%4,%5,%6,%7}, {%8,%9}, {%0,%1,%2,%3};"
        : "+f"(d[0]), "+f"(d[1]), "+f"(d[2]), "+f"(d[3])
        : "r"(a[0]), "r"(a[1]), "r"(a[2]), "r"(a[3]), "r"(b0), "r"(b1));
}
__device__ __forceinline__ void split2(float x, float y, uint32_t& hi, uint32_t& lo) {
    __nv_bfloat162 h = __floats2bfloat162_rn(x, y);
    float xr = x - __bfloat162float(__low2bfloat16(h));
    float yr = y - __bfloat162float(__high2bfloat16(h));
    __nv_bfloat162 l = __floats2bfloat162_rn(xr, yr);
    hi = *(uint32_t*)&h;
    lo = *(uint32_t*)&l;
}

struct WJob { const float* W; __nv_bfloat16* hi; __nv_bfloat16* lo; int K, N, K2, tile0, tilesK; };
struct WJobs { WJob j[8]; };

__global__ void wsplit_all(WJobs jobs)
{
    __shared__ float tile[32][33];
    int b = blockIdx.x;
    int ji = 0;
    #pragma unroll
    for (int i = 1; i < 8; i++) if (b >= jobs.j[i].tile0) ji = i;
    WJob jb = jobs.j[ji];
    int t = b - jb.tile0;
    int kt = (t % jb.tilesK) * 32, nt = (t / jb.tilesK) * 32;
    int tx = threadIdx.x, ty = threadIdx.y;
    #pragma unroll
    for (int i = 0; i < 4; i++) {
        int k = kt + ty + i * 8;
        tile[ty + i * 8][tx] = (k < jb.K) ? jb.W[(size_t)k * jb.N + nt + tx] : 0.f;
    }
    __syncthreads();
    #pragma unroll
    for (int i = 0; i < 4; i++) {
        int n = nt + ty + i * 8;
        int k = kt + tx;
        float v = tile[tx][ty + i * 8];
        __nv_bfloat16 h = __float2bfloat16_rn(v);
        __nv_bfloat16 l = __float2bfloat16_rn(v - __bfloat162float(h));
        jb.hi[(size_t)n * jb.K2 + k] = h;
        jb.lo[(size_t)n * jb.K2 + k] = l;
    }
}

__global__ void ln_kernel(const float* __restrict__ x,
                          const float* __restrict__ gv, const float* __restrict__ bv,
                          const float* __restrict__ gt, const float* __restrict__ bt)
{
    int row = blockIdx.x;
    const float* xr = x + (size_t)row * LD_X;
    float* outr = g_xn + (size_t)row * 1792;
    __shared__ float red[256];
    int tid = threadIdx.x;

    float s = 0.f;
    for (int c = tid; c < DV; c += 256) s += xr[c];
    red[tid] = s; __syncthreads();
    for (int o = 128; o > 0; o >>= 1) { if (tid < o) red[tid] += red[tid + o]; __syncthreads(); }
    float m = red[0] / (float)DV;
    __syncthreads();
    float s2 = 0.f;
    for (int c = tid; c < DV; c += 256) { float d = xr[c] - m; s2 += d * d; }
    red[tid] = s2; __syncthreads();
    for (int o = 128; o > 0; o >>= 1) { if (tid < o) red[tid] += red[tid + o]; __syncthreads(); }
    float r = rsqrtf(red[0] / (float)DV + 1e-5f);
    __syncthreads();
    for (int c = tid; c < DV; c += 256) outr[c] = (xr[c] - m) * r * gv[c] + bv[c];

    s = 0.f;
    for (int c = tid; c < DT; c += 256) s += xr[DV + c];
    red[tid] = s; __syncthreads();
    for (int o = 128; o > 0; o >>= 1) { if (tid < o) red[tid] += red[tid + o]; __syncthreads(); }
    m = red[0] / (float)DT;
    __syncthreads();
    s2 = 0.f;
    for (int c = tid; c < DT; c += 256) { float d = xr[DV + c] - m; s2 += d * d; }
    red[tid] = s2; __syncthreads();
    for (int o = 128; o > 0; o >>= 1) { if (tid < o) red[tid] += red[tid + o]; __syncthreads(); }
    r = rsqrtf(red[0] / (float)DT + 1e-5f);
    __syncthreads();
    for (int c = tid; c < DT; c += 256) outr[DV + c] = (xr[DV + c] - m) * r * gt[c] + bt[c];
}

#define E_BIAS  0
#define E_RELU  1
#define E_RESID 2
#define E_BN    3
#define SRW 20
#define BUFW (128*SRW)
#define GEMM_DSMEM (8 * BUFW * 4)

template<int ASRC>
__device__ __forceinline__ float loadA(const float* __restrict__ A, int lda, int m, int kk, int K)
{
    if (ASRC == 0) return (kk < K) ? A[(size_t)m * lda + kk] : 0.f;
    if (kk < FDIM)      return g_base[(size_t)m * FDIM + kk];
    if (kk < FDIM + CC) return g_cp[(size_t)m * CC + (kk - FDIM)];
    if (kk < GI)        return g_tok[(size_t)m * HH + (kk - FDIM - CC)];
    return 0.f;
}

template<int EPI, int ASRC>
__global__ void __launch_bounds__(256)
gemm_mma(const float* __restrict__ A, int lda,
         const __nv_bfloat16* __restrict__ Whi,
         const __nv_bfloat16* __restrict__ Wlo,
         int K2,
         const float* __restrict__ bias,
         float* __restrict__ C, int ldc,
         int N, int K,
         const float* __restrict__ scale, const float* __restrict__ shift,
         const float* __restrict__ resid, int ldr, float alpha,
         const float* __restrict__ gpp)
{
    extern __shared__ uint32_t dsm[];
    uint32_t* sAhi = dsm;
    uint32_t* sAlo = dsm + 2 * BUFW;
    uint32_t* sBhi = dsm + 4 * BUFW;
    uint32_t* sBlo = dsm + 6 * BUFW;
    uint32_t pbase = smem_u32(dsm);

    int tid = threadIdx.x;
    int lane = tid & 31, wid = tid >> 5;
    int bm = blockIdx.y * 128, bn = blockIdx.x * 128;
    int wm = (wid >> 1) * 32, wn = (wid & 1) * 64;

    float acc[2][8][4];
    #pragma unroll
    for (int mf = 0; mf < 2; mf++)
        #pragma unroll
        for (int nf = 0; nf < 8; nf++)
            #pragma unroll
            for (int q = 0; q < 4; q++) acc[mf][nf][q] = 0.f;

    int a_r = tid >> 3, a_kq = (tid & 7) * 4;
    int b_n = tid & 127, b_kb = (tid >> 7) * 16;

    float aReg[4][4];
    uint4 bh4[2], bl4[2];

    int nch = (K + 31) / 32;
    const bool avec = (ASRC == 0) && ((lda & 3) == 0) && ((K & 31) == 0);

    int aRow = wm + (lane & 7) + ((lane >> 3) & 1) * 8;
    int aKw  = ((lane >> 4) & 1) * 4;
    int bRow = wn + (lane & 7) + ((lane >> 4) & 1) * 8;
    int bKw  = ((lane >> 3) & 1) * 4;

    {
        if (avec) {
            #pragma unroll
            for (int p = 0; p < 4; p++)
                *(float4*)aReg[p] = *(const float4*)&A[(size_t)(bm + a_r + p * 32) * lda + a_kq];
        } else {
            #pragma unroll
            for (int p = 0; p < 4; p++)
                #pragma unroll
                for (int q = 0; q < 4; q++)
                    aReg[p][q] = loadA<ASRC>(A, lda, bm + a_r + p * 32, a_kq + q, K);
        }
        const uint4* ph = (const uint4*)(Whi + (size_t)(bn + b_n) * K2 + b_kb);
        const uint4* pl = (const uint4*)(Wlo + (size_t)(bn + b_n) * K2 + b_kb);
        bh4[0] = ph[0]; bh4[1] = ph[1];
        bl4[0] = pl[0]; bl4[1] = pl[1];
    }

    for (int ch = 0; ch < nch; ch++) {
        int bo = (ch & 1) * BUFW;
        // STS chunk ch into its buffer (disjoint from the buffer being computed)
        #pragma unroll
        for (int p = 0; p < 4; p++) {
            uint32_t h0, l0, h1, l1;
            split2(aReg[p][0], aReg[p][1], h0, l0);
            split2(aReg[p][2], aReg[p][3], h1, l1);
            int idx = bo + (a_r + p * 32) * SRW + (a_kq >> 1);
            *(uint2*)&sAhi[idx] = make_uint2(h0, h1);
            *(uint2*)&sAlo[idx] = make_uint2(l0, l1);
        }
        {
            int idx = bo + b_n * SRW + (b_kb >> 1);
            *(uint4*)&sBhi[idx]     = bh4[0];
            *(uint4*)&sBhi[idx + 4] = bh4[1];
            *(uint4*)&sBlo[idx]     = bl4[0];
            *(uint4*)&sBlo[idx + 4] = bl4[1];
        }
        __syncthreads();   // single barrier per chunk (double-buffered smem)

        // prefetch chunk ch+1 into registers (overlaps compute below)
        if (ch + 1 < nch) {
            int k0 = (ch + 1) * 32;
            if (avec) {
                #pragma unroll
                for (int p = 0; p < 4; p++)
                    *(float4*)aReg[p] = *(const float4*)&A[(size_t)(bm + a_r + p * 32) * lda + k0 + a_kq];
            } else {
                #pragma unroll
                for (int p = 0; p < 4; p++)
                    #pragma unroll
                    for (int q = 0; q < 4; q++)
                        aReg[p][q] = loadA<ASRC>(A, lda, bm + a_r + p * 32, k0 + a_kq + q, K);
            }
            const uint4* ph = (const uint4*)(Whi + (size_t)(bn + b_n) * K2 + k0 + b_kb);
            const uint4* pl = (const uint4*)(Wlo + (size_t)(bn + b_n) * K2 + k0 + b_kb);
            bh4[0] = ph[0]; bh4[1] = ph[1];
            bl4[0] = pl[0]; bl4[1] = pl[1];
        }

        uint32_t pA  = pbase + bo * 4;
        uint32_t pAl = pA + 2 * BUFW * 4;
        uint32_t pB  = pA + 4 * BUFW * 4;
        uint32_t pBl = pA + 6 * BUFW * 4;
        #pragma unroll
        for (int ks = 0; ks < 2; ks++) {
            uint32_t ah[2][4], al[2][4];
            #pragma unroll
            for (int mf = 0; mf < 2; mf++) {
                uint32_t off = (uint32_t)((aRow + mf * 16) * SRW + ks * 8 + aKw) * 4u;
                ldm_x4(ah[mf][0], ah[mf][1], ah[mf][2], ah[mf][3], pA + off);
                ldm_x4(al[mf][0], al[mf][1], al[mf][2], al[mf][3], pAl + off);
            }
            uint32_t bh[8][2], bl[8][2];
            #pragma unroll
            for (int np = 0; np < 4; np++) {
                uint32_t off = (uint32_t)((bRow + np * 16) * SRW + ks * 8 + bKw) * 4u;
                ldm_x4(bh[2 * np][0], bh[2 * np][1], bh[2 * np + 1][0], bh[2 * np + 1][1], pB + off);
                ldm_x4(bl[2 * np][0], bl[2 * np][1], bl[2 * np + 1][0], bl[2 * np + 1][1], pBl + off);
            }
            #pragma unroll
            for (int nf = 0; nf < 8; nf++) {
                #pragma unroll
                for (int mf = 0; mf < 2; mf++) {
                    mma16816(acc[mf][nf], ah[mf], bh[nf][0], bh[nf][1]);
                    mma16816(acc[mf][nf], ah[mf], bl[nf][0], bl[nf][1]);
                    mma16816(acc[mf][nf], al[mf], bh[nf][0], bh[nf][1]);
                }
            }
        }
        // no trailing barrier: next iteration writes the OTHER buffer
    }

    int mb = bm + wm + (lane >> 2);
    int nb = bn + wn + 2 * (lane & 3);
    #pragma unroll
    for (int mf = 0; mf < 2; mf++) {
        #pragma unroll
        for (int nf = 0; nf < 8; nf++) {
            int n0 = nb + nf * 8;
            #pragma unroll
            for (int half = 0; half < 2; half++) {
                int m = mb + mf * 16 + half * 8;
                float v0 = acc[mf][nf][half * 2 + 0] + bias[n0];
                float v1 = acc[mf][nf][half * 2 + 1] + bias[n0 + 1];
                if (EPI == E_RELU) { v0 = fmaxf(v0, 0.f); v1 = fmaxf(v1, 0.f); }
                else if (EPI == E_RESID) {
                    float g = gpp[(size_t)m * 2 + (n0 >= HH ? 1 : 0)];
                    v0 = resid[(size_t)m * ldr + n0] * g + alpha * v0;
                    v1 = resid[(size_t)m * ldr + n0 + 1] * g + alpha * v1;
                }
                else if (EPI == E_BN) {
                    float rs = rsqrtf(1.f + 1e-5f);
                    v0 = fmaxf(v0 * (scale[n0] * rs) + shift[n0], 0.f);
                    v1 = fmaxf(v1 * (scale[n0 + 1] * rs) + shift[n0 + 1], 0.f);
                }
                *(float2*)&C[(size_t)m * ldc + n0] = make_float2(v0, v1);
            }
        }
    }
}

__global__ void cp_kernel(const float* __restrict__ Wcp, const float* __restrict__ bcp)
{
    int warp = threadIdx.x >> 5, lane = threadIdx.x & 31;
    int row = blockIdx.x * 8 + warp;
    if (row >= BB) return;
    const float* f = g_base + (size_t)row * FDIM;
    float acc[CC] = {0, 0, 0, 0, 0};
    for (int k = lane; k < FDIM; k += 32) {
        float fv = f[k];
        #pragma unroll
        for (int c = 0; c < CC; c++) acc[c] += fv * Wcp[k * CC + c];
    }
    #pragma unroll
    for (int c = 0; c < CC; c++)
        for (int o = 16; o; o >>= 1) acc[c] += __shfl_xor_sync(0xffffffff, acc[c], o);
    if (lane == 0) {
        float z[CC], mx = -1e30f, sum = 0.f;
        #pragma unroll
        for (int c = 0; c < CC; c++) { z[c] = acc[c] + bcp[c]; mx = fmaxf(mx, z[c]); }
        #pragma unroll
        for (int c = 0; c < CC; c++) { z[c] = expf(z[c] - mx); sum += z[c]; }
        #pragma unroll
        for (int c = 0; c < CC; c++) g_cp[(size_t)row * CC + c] = z[c] / sum;
    }
}

__global__ void zero_cnt_kernel() {
    int t = blockIdx.x * blockDim.x + threadIdx.x;
    if (t < NIMG) { g_cnt[t] = 0; g_cur[t] = 0; }
}
__global__ void count_kernel(const float* __restrict__ x) {
    int i = blockIdx.x * blockDim.x + threadIdx.x;
    if (i >= BB) return;
    int im = (int)x[(size_t)i * LD_X + 1796];
    atomicAdd(&g_cnt[im], 1);
}
__global__ void prefix_kernel() {
    if (blockIdx.x == 0 && threadIdx.x == 0) {
        int s = 0;
        for (int i = 0; i < NIMG; i++) { g_off[i] = s; s += g_cnt[i]; }
        g_off[NIMG] = s;
    }
}
__global__ void fill_kernel(const float* __restrict__ x) {
    int i = blockIdx.x * blockDim.x + threadIdx.x;
    if (i >= BB) return;
    int im = (int)x[(size_t)i * LD_X + 1796];
    int p = atomicAdd(&g_cur[im], 1);
    g_bucket[g_off[im] + p] = i;
}

__device__ __forceinline__ void topk_insert(float* val, int* ind, float s, int j) {
    if (s > val[KNN - 1]) {
        int p = KNN - 1;
        while (p > 0 && s > val[p - 1]) { val[p] = val[p - 1]; ind[p] = ind[p - 1]; p--; }
        val[p] = s; ind[p] = j;
    }
}

__global__ void knn_topk_kernel(const float* __restrict__ x)
{
    int i = blockIdx.x * blockDim.x + threadIdx.x;
    if (i >= BB) return;
    const float* xi = x + (size_t)i * LD_X;
    float cx = xi[1792], cy = xi[1793];
    int im = (int)xi[1796];
    float sqi = cx * cx + cy * cy;

    float val[KNN]; int ind[KNN];
    #pragma unroll
    for (int k = 0; k < KNN; k++) { val[k] = NEGV; ind[k] = 0; }

    int s = g_off[im], e = g_off[im + 1];
    int m = 0;
    for (int p = s; p < e; p++) {
        int j = g_bucket[p];
        if (j == i) continue;
        const float* xj = x + (size_t)j * LD_X;
        float jx = xj[1792], jy = xj[1793];
        float sqj = jx * jx + jy * jy;
        float d2 = sqi + sqj - 2.f * (cx * jx + cy * jy);
        float sim = -sqrtf(fmaxf(d2, 0.f));
        m++;
        topk_insert(val, ind, sim, j);
    }
    if (m == 0) {
        for (int j = 0; j < BB; j++) {
            if (j == i) continue;
            const float* xj = x + (size_t)j * LD_X;
            float jx = xj[1792], jy = xj[1793];
            float sqj = jx * jx + jy * jy;
            float d2 = sqi + sqj - 2.f * (cx * jx + cy * jy);
            float sim = -sqrtf(fmaxf(d2, 0.f));
            topk_insert(val, ind, sim, j);
        }
    }
    float mx = val[0];
    float w[KNN], sum = 0.f;
    #pragma unroll
    for (int k = 0; k < KNN; k++) { w[k] = expf(val[k] - mx); sum += w[k]; }
    float inv = 1.f / sum;
    #pragma unroll
    for (int k = 0; k < KNN; k++) {
        g_w[(size_t)i * KNN + k] = w[k] * inv;
        g_nidx[(size_t)i * KNN + k] = ind[k];
    }
}

__global__ void gather_kernel(const float* __restrict__ F, float* __restrict__ out,
                              const float* __restrict__ gp, int gated)
{
    int row = blockIdx.x;
    __shared__ float sw0[KNN], sw1[KNN];
    __shared__ int   si[KNN];
    if (threadIdx.x < KNN) {
        int k = threadIdx.x;
        float w = g_w[(size_t)row * KNN + k];
        int j = g_nidx[(size_t)row * KNN + k];
        si[k] = j;
        if (gated) { sw0[k] = w * gp[(size_t)j * 2]; sw1[k] = w * gp[(size_t)j * 2 + 1]; }
        else       { sw0[k] = w; sw1[k] = w; }
    }
    __syncthreads();
    for (int c = threadIdx.x; c < FDIM; c += blockDim.x) {
        const float* s = (c < HH) ? sw0 : sw1;
        float acc = 0.f;
        #pragma unroll
        for (int k = 0; k < KNN; k++) acc += s[k] * F[(size_t)si[k] * FDIM + c];
        out[(size_t)row * FDIM + c] = acc;
    }
}

__global__ void gate2_kernel(const float* __restrict__ Wg2, const float* __restrict__ bg2)
{
    int warp = threadIdx.x >> 5, lane = threadIdx.x & 31;
    int row = blockIdx.x * 8 + warp;
    if (row >= BB) return;
    float a0 = 0.f, a1 = 0.f;
    const float* h = g_hid + (size_t)row * GHH;
    for (int k = lane; k < GHH; k += 32) {
        float hv = h[k];
        a0 += hv * Wg2[k * 2];
        a1 += hv * Wg2[k * 2 + 1];
    }
    for (int o = 16; o; o >>= 1) {
        a0 += __shfl_xor_sync(0xffffffff, a0, o);
        a1 += __shfl_xor_sync(0xffffffff, a1, o);
    }
    if (lane == 0) {
        float z0 = a0 + bg2[0], z1 = a1 + bg2[1];
        float mx = fmaxf(z0, z1);
        float e0 = expf(z0 - mx), e1 = expf(z1 - mx);
        float sinv = 1.f / (e0 + e1);
        float p0 = e0 * sinv, p1 = e1 * sinv;
        g_gp[(size_t)row * 2] = p0;
        g_gp[(size_t)row * 2 + 1] = p1;
        g_ent[row] = -(p0 * logf(p0 + 1e-8f) + p1 * logf(p1 + 1e-8f));
    }
}

__global__ void c2_kernel(const float* __restrict__ Wc2, const float* __restrict__ bc2,
                          float* __restrict__ out)
{
    int warp = threadIdx.x >> 5, lane = threadIdx.x & 31;
    int row = blockIdx.x * 8 + warp;
    if (row >= BB) return;
    const float* h = g_h + (size_t)row * HH;
    float acc[CC] = {0, 0, 0, 0, 0};
    for (int k = lane; k < HH; k += 32) {
        float hv = h[k];
        #pragma unroll
        for (int c = 0; c < CC; c++) acc[c] += hv * Wc2[k * CC + c];
    }
    #pragma unroll
    for (int c = 0; c < CC; c++)
        for (int o = 16; o; o >>= 1) acc[c] += __shfl_xor_sync(0xffffffff, acc[c], o);
    if (lane == 0) {
        #pragma unroll
        for (int c = 0; c < CC; c++) out[(size_t)row * CC + c] = acc[c] + bc2[c];
    }
}

__global__ void ent_reduce_kernel(float* __restrict__ out)
{
    __shared__ float red[256];
    int tid = threadIdx.x;
    float s = 0.f;
    for (int t = tid; t < BB; t += 256) s += g_ent[t];
    red[tid] = s; __syncthreads();
    for (int o = 128; o > 0; o >>= 1) { if (tid < o) red[tid] += red[tid + o]; __syncthreads(); }
    if (tid == 0) out[0] = red[0] / (float)BB * 0.01f;
}

static float* sym_f(const void* p) { return (float*)p; }

extern "C" void kernel_launch(void* const* d_in, const int* in_sizes, int n_in,
                              void* d_out, int out_size)
{
    const float* x     = (const float*)d_in[0];
    const float* ln_vg = (const float*)d_in[1];
    const float* ln_vb = (const float*)d_in[2];
    const float* ln_tg = (const float*)d_in[3];
    const float* ln_tb = (const float*)d_in[4];
    const float* W_v   = (const float*)d_in[5];
    const float* b_v   = (const float*)d_in[6];
    const float* W_t   = (const float*)d_in[7];
    const float* b_t   = (const float*)d_in[8];
    const float* W_cp  = (const float*)d_in[9];
    const float* b_cp  = (const float*)d_in[10];
    const float* W_ctx1 = (const float*)d_in[11];
    const float* b_ctx1 = (const float*)d_in[12];
    const float* W_ctx2 = (const float*)d_in[13];
    const float* b_ctx2 = (const float*)d_in[14];
    const float* W_g1  = (const float*)d_in[15];
    const float* b_g1  = (const float*)d_in[16];
    const float* W_g2  = (const float*)d_in[17];
    const float* b_g2  = (const float*)d_in[18];
    const float* W_gu1 = (const float*)d_in[19];
    const float* b_gu1 = (const float*)d_in[20];
    const float* W_gu2 = (const float*)d_in[21];
    const float* b_gu2 = (const float*)d_in[22];
    const float* W_c1  = (const float*)d_in[23];
    const float* b_c1  = (const float*)d_in[24];
    const float* bn_g  = (const float*)d_in[25];
    const float* bn_b  = (const float*)d_in[26];
    const float* W_c2  = (const float*)d_in[27];
    const float* b_c2  = (const float*)d_in[28];
    float* out = (float*)d_out;

    void *p_xn, *p_base, *p_agg, *p_t1, *p_tok, *p_hid, *p_fused, *p_u1, *p_h, *p_gp;
    void *p_whi, *p_wlo;
    cudaGetSymbolAddress(&p_xn, g_xn);
    cudaGetSymbolAddress(&p_base, g_base);
    cudaGetSymbolAddress(&p_agg, g_agg);
    cudaGetSymbolAddress(&p_t1, g_t1);
    cudaGetSymbolAddress(&p_tok, g_tok);
    cudaGetSymbolAddress(&p_hid, g_hid);
    cudaGetSymbolAddress(&p_fused, g_fused);
    cudaGetSymbolAddress(&p_u1, g_u1);
    cudaGetSymbolAddress(&p_h, g_h);
    cudaGetSymbolAddress(&p_gp, g_gp);
    cudaGetSymbolAddress(&p_whi, g_whi);
    cudaGetSymbolAddress(&p_wlo, g_wlo);
    float* xn    = sym_f(p_xn);
    float* base  = sym_f(p_base);
    float* agg   = sym_f(p_agg);
    float* t1    = sym_f(p_t1);
    float* tok   = sym_f(p_tok);
    float* hid   = sym_f(p_hid);
    float* fused = sym_f(p_fused);
    float* u1    = sym_f(p_u1);
    float* hbuf  = sym_f(p_h);
    float* gp    = sym_f(p_gp);
    __nv_bfloat16* whi = (__nv_bfloat16*)p_whi;
    __nv_bfloat16* wlo = (__nv_bfloat16*)p_wlo;

    cudaFuncSetAttribute(gemm_mma<E_BIAS, 0>,  cudaFuncAttributeMaxDynamicSharedMemorySize, GEMM_DSMEM);
    cudaFuncSetAttribute(gemm_mma<E_RELU, 0>,  cudaFuncAttributeMaxDynamicSharedMemorySize, GEMM_DSMEM);
    cudaFuncSetAttribute(gemm_mma<E_RELU, 1>,  cudaFuncAttributeMaxDynamicSharedMemorySize, GEMM_DSMEM);
    cudaFuncSetAttribute(gemm_mma<E_RESID, 0>, cudaFuncAttributeMaxDynamicSharedMemorySize, GEMM_DSMEM);
    cudaFuncSetAttribute(gemm_mma<E_BN, 0>,    cudaFuncAttributeMaxDynamicSharedMemorySize, GEMM_DSMEM);

    WJobs jobs;
    int t0 = 0;
    auto setj = [&](int i, const float* W, int off, int K, int N, int K2) {
        jobs.j[i] = WJob{ W, whi + off, wlo + off, K, N, K2, t0, K2 / 32 };
        t0 += (K2 / 32) * (N / 32);
    };
    setj(0, W_v,    OW_V,   DV,   HH,   1024);
    setj(1, W_t,    OW_T,   DT,   HH,   768);
    setj(2, W_ctx1, OW_C1,  FDIM, HH,   512);
    setj(3, W_ctx2, OW_C2,  HH,   HH,   256);
    setj(4, W_g1,   OW_G1,  GI,   GHH,  800);
    setj(5, W_gu1,  OW_U1,  FDIM, FDIM, 512);
    setj(6, W_gu2,  OW_U2,  FDIM, FDIM, 512);
    setj(7, W_c1,   OW_CL1, FDIM, HH,   512);
    wsplit_all<<<t0, dim3(32, 8)>>>(jobs);

    ln_kernel<<<BB, 256>>>(x, ln_vg, ln_vb, ln_tg, ln_tb);

    dim3 gA(HH / 128, BB / 128);
    gemm_mma<E_BIAS, 0><<<gA, 256, GEMM_DSMEM>>>(xn, 1792, whi + OW_V, wlo + OW_V, 1024, b_v,
        base, FDIM, HH, DV, nullptr, nullptr, nullptr, 0, 0.f, nullptr);
    gemm_mma<E_BIAS, 0><<<gA, 256, GEMM_DSMEM>>>(xn + DV, 1792, whi + OW_T, wlo + OW_T, 768, b_t,
        base + HH, FDIM, HH, DT, nullptr, nullptr, nullptr, 0, 0.f, nullptr);

    cp_kernel<<<BB / 8, 256>>>(W_cp, b_cp);

    zero_cnt_kernel<<<2, 256>>>();
    count_kernel<<<BB / 256, 256>>>(x);
    prefix_kernel<<<1, 32>>>();
    fill_kernel<<<BB / 256, 256>>>(x);
    knn_topk_kernel<<<BB / 256, 256>>>(x);

    gather_kernel<<<BB, 128>>>(base, agg, nullptr, 0);
    gemm_mma<E_RELU, 0><<<gA, 256, GEMM_DSMEM>>>(agg, FDIM, whi + OW_C1, wlo + OW_C1, 512, b_ctx1,
        t1, HH, HH, FDIM, nullptr, nullptr, nullptr, 0, 0.f, nullptr);
    gemm_mma<E_BIAS, 0><<<gA, 256, GEMM_DSMEM>>>(t1, HH, whi + OW_C2, wlo + OW_C2, 256, b_ctx2,
        tok, HH, HH, HH, nullptr, nullptr, nullptr, 0, 0.f, nullptr);

    // gate: A composed on the fly from [base | cp | tok]
    dim3 gG(GHH / 128, BB / 128);
    gemm_mma<E_RELU, 1><<<gG, 256, GEMM_DSMEM>>>(nullptr, 0, whi + OW_G1, wlo + OW_G1, 800, b_g1,
        hid, GHH, GHH, GI, nullptr, nullptr, nullptr, 0, 0.f, nullptr);
    gate2_kernel<<<BB / 8, 256>>>(W_g2, b_g2);

    // gated gather -> upd -> fused = base*gp + 0.5*upd
    gather_kernel<<<BB, 128>>>(base, agg, gp, 1);
    dim3 gF(FDIM / 128, BB / 128);
    gemm_mma<E_RELU, 0><<<gF, 256, GEMM_DSMEM>>>(agg, FDIM, whi + OW_U1, wlo + OW_U1, 512, b_gu1,
        u1, FDIM, FDIM, FDIM, nullptr, nullptr, nullptr, 0, 0.f, nullptr);
    gemm_mma<E_RESID, 0><<<gF, 256, GEMM_DSMEM>>>(u1, FDIM, whi + OW_U2, wlo + OW_U2, 512, b_gu2,
        fused, FDIM, FDIM, FDIM, nullptr, nullptr, base, FDIM, 0.5f, gp);

    gemm_mma<E_BN, 0><<<gA, 256, GEMM_DSMEM>>>(fused, FDIM, whi + OW_CL1, wlo + OW_CL1, 512, b_c1,
        hbuf, HH, HH, FDIM, bn_g, bn_b, nullptr, 0, 0.f, nullptr);
    c2_kernel<<<BB / 8, 256>>>(W_c2, b_c2, out);

    ent_reduce_kernel<<<1, 256>>>(out + (out_size - 1));
}